// round 1
// baseline (speedup 1.0000x reference)
#include <cuda_runtime.h>
#include <math.h>

#define BB 16
#define LQ 64
#define LD 2048
#define HH 1024
#define DIM 128
#define MAXK_MAX 2049   // LD/pf + 1 with pf >= 1

// ---------------- scratch (device globals; no allocation) ----------------
__device__ float    g_d[(size_t)BB * LD * DIM];            // encoded docs      16 MB
__device__ float    g_qT[(size_t)BB * DIM * LQ];           // encoded q, T      512 KB
__device__ float    g_sums[(size_t)BB * MAXK_MAX * DIM];   // segment sums      16.8 MB
__device__ float    g_counts[(size_t)BB * MAXK_MAX];
__device__ float    g_pool[(size_t)BB * MAXK_MAX * DIM];   // pooled & normed
__device__ int      g_k[BB];
__device__ unsigned g_simmax[BB * LQ];

// ---------------- float <-> orderable-uint encoding for atomicMax --------
__device__ __forceinline__ unsigned enc_f(float f) {
    int b = __float_as_int(f);
    return (unsigned)(b ^ ((b >> 31) | 0x80000000));
}
__device__ __forceinline__ float dec_f(unsigned u) {
    int b = (u & 0x80000000u) ? (int)(u ^ 0x80000000u) : ~(int)u;
    return __int_as_float(b);
}

// ---------------- init: zero accumulators, init max slots ----------------
__global__ void init_kernel() {
    size_t i = (size_t)blockIdx.x * blockDim.x + threadIdx.x;
    size_t stride = (size_t)gridDim.x * blockDim.x;
    const size_t nsum = (size_t)BB * MAXK_MAX * DIM;
    for (size_t j = i; j < nsum; j += stride) g_sums[j] = 0.0f;
    for (size_t j = i; j < (size_t)BB * MAXK_MAX; j += stride) g_counts[j] = 0.0f;
    unsigned neg = enc_f(-1e4f);
    for (size_t j = i; j < (size_t)BB * LQ; j += stride) g_simmax[j] = neg;
}

// ---------------- per-batch cluster count k ----------------
__global__ void k_kernel(const int* __restrict__ dmask, const int* __restrict__ pfp) {
    int b = blockIdx.x;
    int s = 0;
    for (int i = threadIdx.x; i < LD; i += 256) s += dmask[b * LD + i];
    #pragma unroll
    for (int off = 16; off; off >>= 1) s += __shfl_xor_sync(0xffffffffu, s, off);
    __shared__ int sm[8];
    int warp = threadIdx.x >> 5, lane = threadIdx.x & 31;
    if (lane == 0) sm[warp] = s;
    __syncthreads();
    if (threadIdx.x == 0) {
        int tot = 0;
        #pragma unroll
        for (int w = 0; w < 8; w++) tot += sm[w];
        int pf = pfp ? pfp[0] : 4;
        if (pf < 1) pf = 1;
        int valid = tot < 2 ? 2 : tot;
        g_k[b] = valid / pf + 1;
    }
}

// ---------------- fused encode: GEMM + bias + L2 norm + mask -------------
// 256 threads, BM=64 rows x BN=128 cols, BK=32. warp owns 8 rows, lane 4 cols.
__global__ __launch_bounds__(256) void encode_kernel(
    const float* __restrict__ qh, const float* __restrict__ dh,
    const float* __restrict__ Wm, const float* __restrict__ bias,
    const int* __restrict__ qmask, const int* __restrict__ dmask)
{
    const int blockRow = blockIdx.x * 64;
    const bool isQ = blockRow < BB * LQ;
    const float* src;
    const int* mask;
    if (isQ) { src = qh + (size_t)blockRow * HH; mask = qmask + blockRow; }
    else {
        int r = blockRow - BB * LQ;
        src = dh + (size_t)r * HH; mask = dmask + r;
    }

    __shared__ float As[64][40];   // [row][k], padded: conflict-free f4 stores
    __shared__ float Bs[32][128];  // [k][col]

    const int tid  = threadIdx.x;
    const int warp = tid >> 5, lane = tid & 31;
    const int rowBase = warp * 8;
    const int colBase = lane * 4;

    float acc[8][4];
    #pragma unroll
    for (int r = 0; r < 8; r++)
        #pragma unroll
        for (int j = 0; j < 4; j++) acc[r][j] = 0.0f;

    for (int k0 = 0; k0 < HH; k0 += 32) {
        // A tile: 64x32 -> 512 float4 slots, 2 per thread
        #pragma unroll
        for (int i = 0; i < 2; i++) {
            int s = tid + 256 * i;
            int r = s >> 3, kk = (s & 7) * 4;
            float4 v = *(const float4*)(src + (size_t)r * HH + k0 + kk);
            *(float4*)&As[r][kk] = v;
        }
        // B tile: 32x128 -> 1024 float4 slots, 4 per thread
        #pragma unroll
        for (int i = 0; i < 4; i++) {
            int s = tid + 256 * i;
            int kk = s >> 5, c = (s & 31) * 4;
            float4 v = *(const float4*)(Wm + (size_t)(k0 + kk) * DIM + c);
            *(float4*)&Bs[kk][c] = v;
        }
        __syncthreads();
        #pragma unroll
        for (int kk = 0; kk < 32; kk++) {
            float4 bv = *(const float4*)&Bs[kk][colBase];
            #pragma unroll
            for (int r = 0; r < 8; r++) {
                float a = As[rowBase + r][kk];
                acc[r][0] += a * bv.x; acc[r][1] += a * bv.y;
                acc[r][2] += a * bv.z; acc[r][3] += a * bv.w;
            }
        }
        __syncthreads();
    }

    float4 b4 = *(const float4*)(bias + colBase);
    #pragma unroll
    for (int r = 0; r < 8; r++) {
        float v0 = acc[r][0] + b4.x, v1 = acc[r][1] + b4.y;
        float v2 = acc[r][2] + b4.z, v3 = acc[r][3] + b4.w;
        float ss = v0 * v0 + v1 * v1 + v2 * v2 + v3 * v3;
        #pragma unroll
        for (int off = 16; off; off >>= 1) ss += __shfl_xor_sync(0xffffffffu, ss, off);
        float inv = 1.0f / fmaxf(sqrtf(ss), 1e-12f);
        float m = (float)mask[rowBase + r];
        float s = inv * m;
        if (isQ) {
            int b   = blockRow / LQ;       // blockRow % 64 == 0
            int row = rowBase + r;
            float* q = g_qT + (size_t)b * DIM * LQ;
            q[(colBase + 0) * LQ + row] = v0 * s;
            q[(colBase + 1) * LQ + row] = v1 * s;
            q[(colBase + 2) * LQ + row] = v2 * s;
            q[(colBase + 3) * LQ + row] = v3 * s;
        } else {
            float4 o = make_float4(v0 * s, v1 * s, v2 * s, v3 * s);
            float* dst = g_d + (size_t)(blockRow - BB * LQ + rowBase + r) * DIM;
            *(float4*)(dst + colBase) = o;
        }
    }
}

// ---------------- segment-sum via atomics (one warp per token) -----------
__global__ void pool_accum_kernel(const int* __restrict__ dmask,
                                  const int* __restrict__ labels)
{
    int gwarp = (blockIdx.x * blockDim.x + threadIdx.x) >> 5;
    if (gwarp >= BB * LD) return;
    int b = gwarp / LD, t = gwarp % LD;
    if (dmask[b * LD + t] <= 0) return;    // warp-uniform
    int lane = threadIdx.x & 31;
    int seg  = labels[b * LD + t] % g_k[b];
    const float4 v = *(const float4*)(g_d + ((size_t)b * LD + t) * DIM + lane * 4);
    float* dst = g_sums + ((size_t)b * MAXK_MAX + seg) * DIM + lane * 4;
    atomicAdd(dst + 0, v.x); atomicAdd(dst + 1, v.y);
    atomicAdd(dst + 2, v.z); atomicAdd(dst + 3, v.w);
    if (lane == 0) atomicAdd(&g_counts[b * MAXK_MAX + seg], 1.0f);
}

// ---------------- mean + L2 normalize pooled clusters --------------------
__global__ void pool_norm_kernel() {
    int b = blockIdx.y, c = blockIdx.x;
    if (c >= g_k[b]) return;
    int t = threadIdx.x;  // 128 threads = dims
    float cnt = fmaxf(g_counts[b * MAXK_MAX + c], 1.0f);
    float v = g_sums[((size_t)b * MAXK_MAX + c) * DIM + t] / cnt;
    float ss = v * v;
    #pragma unroll
    for (int off = 16; off; off >>= 1) ss += __shfl_xor_sync(0xffffffffu, ss, off);
    __shared__ float red[4];
    int warp = t >> 5, lane = t & 31;
    if (lane == 0) red[warp] = ss;
    __syncthreads();
    float tot = red[0] + red[1] + red[2] + red[3];
    float inv = 1.0f / fmaxf(sqrtf(tot), 1e-12f);
    g_pool[((size_t)b * MAXK_MAX + c) * DIM + t] = v * inv;
}

// ---------------- sim GEMM (64 clusters x 64 q, K=128) + running max -----
__global__ __launch_bounds__(256) void score_kernel() {
    const int b  = blockIdx.y;
    const int kb = g_k[b];
    const int c0 = blockIdx.x * 64;
    if (c0 >= kb) return;

    __shared__ float As[64][40];  // pool [cluster][kk] chunk
    __shared__ float Bs[32][64];  // qT [kk][q] chunk

    const int tid  = threadIdx.x;
    const int warp = tid >> 5, lane = tid & 31;
    const int rowBase = warp * 8;   // clusters
    const int colBase = lane * 2;   // q

    float acc[8][2];
    #pragma unroll
    for (int r = 0; r < 8; r++) { acc[r][0] = 0.0f; acc[r][1] = 0.0f; }

    const float* poolB = g_pool + (size_t)b * MAXK_MAX * DIM;
    const float* qT    = g_qT + (size_t)b * DIM * LQ;

    for (int k0 = 0; k0 < DIM; k0 += 32) {
        #pragma unroll
        for (int i = 0; i < 2; i++) {
            int s = tid + 256 * i;
            int r = s >> 3, kk = (s & 7) * 4;
            float4 v = make_float4(0.f, 0.f, 0.f, 0.f);
            if (c0 + r < kb)
                v = *(const float4*)(poolB + (size_t)(c0 + r) * DIM + k0 + kk);
            *(float4*)&As[r][kk] = v;
        }
        #pragma unroll
        for (int i = 0; i < 2; i++) {
            int s = tid + 256 * i;
            int kk = s >> 4, q4 = (s & 15) * 4;
            float4 v = *(const float4*)(qT + (size_t)(k0 + kk) * LQ + q4);
            *(float4*)&Bs[kk][q4] = v;
        }
        __syncthreads();
        #pragma unroll
        for (int kk = 0; kk < 32; kk++) {
            float2 bv = *(const float2*)&Bs[kk][colBase];
            #pragma unroll
            for (int r = 0; r < 8; r++) {
                float a = As[rowBase + r][kk];
                acc[r][0] += a * bv.x;
                acc[r][1] += a * bv.y;
            }
        }
        __syncthreads();
    }

    float m0 = -1e4f, m1 = -1e4f;
    #pragma unroll
    for (int r = 0; r < 8; r++) {
        if (c0 + rowBase + r < kb) {
            m0 = fmaxf(m0, acc[r][0]);
            m1 = fmaxf(m1, acc[r][1]);
        }
    }
    atomicMax(&g_simmax[b * LQ + colBase],     enc_f(m0));
    atomicMax(&g_simmax[b * LQ + colBase + 1], enc_f(m1));
}

// ---------------- finalize: decode max, mask, sum over q -----------------
__global__ void finalize_kernel(const int* __restrict__ qmask, float* __restrict__ out) {
    int b = blockIdx.x, q = threadIdx.x;  // 64 threads
    float v = dec_f(g_simmax[b * LQ + q]) * (float)qmask[b * LQ + q];
    #pragma unroll
    for (int off = 16; off; off >>= 1) v += __shfl_xor_sync(0xffffffffu, v, off);
    __shared__ float sm[2];
    int warp = q >> 5, lane = q & 31;
    if (lane == 0) sm[warp] = v;
    __syncthreads();
    if (q == 0) out[b] = sm[0] + sm[1];
}

// ---------------- launch ----------------
extern "C" void kernel_launch(void* const* d_in, const int* in_sizes, int n_in,
                              void* d_out, int out_size)
{
    const float* qh    = (const float*)d_in[0];
    const float* dh    = (const float*)d_in[1];
    const float* Wm    = (const float*)d_in[2];
    const float* bias  = (const float*)d_in[3];
    const int*   qmask = (const int*)d_in[4];
    const int*   dmask = (const int*)d_in[5];
    const int*   labels= (const int*)d_in[6];
    const int*   pfp   = (n_in > 7) ? (const int*)d_in[7] : nullptr;
    float* out = (float*)d_out;

    init_kernel<<<4096, 256>>>();
    k_kernel<<<BB, 256>>>(dmask, pfp);
    encode_kernel<<<(BB * LQ + BB * LD) / 64, 256>>>(qh, dh, Wm, bias, qmask, dmask);
    pool_accum_kernel<<<BB * LD / 8, 256>>>(dmask, labels);
    {
        dim3 grid(MAXK_MAX, BB);
        pool_norm_kernel<<<grid, 128>>>();
    }
    {
        dim3 grid((MAXK_MAX + 63) / 64, BB);
        score_kernel<<<grid, 256>>>();
    }
    finalize_kernel<<<BB, 64>>>(qmask, out);
}

// round 3
// speedup vs baseline: 1.5221x; 1.5221x over previous
#include <cuda_runtime.h>
#include <cuda_bf16.h>
#include <math.h>
#include <stdint.h>

#define BB 16
#define LQ 64
#define LD 2048
#define HH 1024
#define DIM 128
#define MAXK_MAX 2049
#define QROWS (BB * LQ)              // 1024
#define NROWS (BB * LQ + BB * LD)    // 33792

// ---------------- scratch (device globals; no allocation) ----------------
__device__ float    g_d[(size_t)BB * LD * DIM];
__device__ float    g_qT[(size_t)BB * DIM * LQ];
__device__ float    g_sums[(size_t)BB * MAXK_MAX * DIM];
__device__ float    g_counts[(size_t)BB * MAXK_MAX];
__device__ float    g_pool[(size_t)BB * MAXK_MAX * DIM];
__device__ int      g_k[BB];
__device__ unsigned g_simmax[BB * LQ];
__device__ __nv_bfloat16 g_Whi[(size_t)DIM * HH];   // W transposed [n][k], hi
__device__ __nv_bfloat16 g_Wlo[(size_t)DIM * HH];   // lo part

// ---------------- helpers ----------------
__device__ __forceinline__ uint32_t smem_u32(const void* p) {
    uint32_t a;
    asm("{ .reg .u64 t; cvta.to.shared.u64 t, %1; cvt.u32.u64 %0, t; }" : "=r"(a) : "l"(p));
    return a;
}
__device__ __forceinline__ void ldmx4(uint32_t* r, uint32_t a) {
    asm volatile("ldmatrix.sync.aligned.m8n8.x4.shared.b16 {%0,%1,%2,%3}, [%4];"
        : "=r"(r[0]), "=r"(r[1]), "=r"(r[2]), "=r"(r[3]) : "r"(a));
}
__device__ __forceinline__ void mma16816(float* d, const uint32_t* a, const uint32_t* b) {
    asm volatile("mma.sync.aligned.m16n8k16.row.col.f32.bf16.bf16.f32 "
        "{%0,%1,%2,%3}, {%4,%5,%6,%7}, {%8,%9}, {%0,%1,%2,%3};"
        : "+f"(d[0]), "+f"(d[1]), "+f"(d[2]), "+f"(d[3])
        : "r"(a[0]), "r"(a[1]), "r"(a[2]), "r"(a[3]), "r"(b[0]), "r"(b[1]));
}
__device__ __forceinline__ void cp16(uint32_t s, const void* g) {
    uint64_t ga = (uint64_t)__cvta_generic_to_global(g);
    asm volatile("cp.async.cg.shared.global [%0], [%1], 16;" :: "r"(s), "l"(ga) : "memory");
}
#define CP_COMMIT() asm volatile("cp.async.commit_group;" ::: "memory")
#define CP_WAIT0()  asm volatile("cp.async.wait_group 0;" ::: "memory")

__device__ __forceinline__ uint32_t pack_bf2(float x, float y) {
    __nv_bfloat162 t(__float2bfloat16_rn(x), __float2bfloat16_rn(y));
    return *(uint32_t*)&t;
}

// ---------------- float <-> orderable-uint for atomicMax ----------------
__device__ __forceinline__ unsigned enc_f(float f) {
    int b = __float_as_int(f);
    return (unsigned)(b ^ ((b >> 31) | 0x80000000));
}
__device__ __forceinline__ float dec_f(unsigned u) {
    int b = (u & 0x80000000u) ? (int)(u ^ 0x80000000u) : ~(int)u;
    return __int_as_float(b);
}

// ---------------- init ----------------
__global__ void init_kernel() {
    size_t i = (size_t)blockIdx.x * blockDim.x + threadIdx.x;
    size_t stride = (size_t)gridDim.x * blockDim.x;
    const size_t nsum = (size_t)BB * MAXK_MAX * DIM;
    for (size_t j = i; j < nsum; j += stride) g_sums[j] = 0.0f;
    for (size_t j = i; j < (size_t)BB * MAXK_MAX; j += stride) g_counts[j] = 0.0f;
    unsigned neg = enc_f(-1e4f);
    for (size_t j = i; j < (size_t)BB * LQ; j += stride) g_simmax[j] = neg;
}

// ---------------- per-batch cluster count ----------------
__global__ void k_kernel(const int* __restrict__ dmask, const int* __restrict__ pfp) {
    int b = blockIdx.x;
    int s = 0;
    for (int i = threadIdx.x; i < LD; i += 256) s += dmask[b * LD + i];
    #pragma unroll
    for (int off = 16; off; off >>= 1) s += __shfl_xor_sync(0xffffffffu, s, off);
    __shared__ int sm[8];
    int warp = threadIdx.x >> 5, lane = threadIdx.x & 31;
    if (lane == 0) sm[warp] = s;
    __syncthreads();
    if (threadIdx.x == 0) {
        int tot = 0;
        #pragma unroll
        for (int w = 0; w < 8; w++) tot += sm[w];
        int pf = pfp ? pfp[0] : 4;
        if (pf < 1) pf = 1;
        int valid = tot < 2 ? 2 : tot;
        g_k[b] = valid / pf + 1;
    }
}

// ---------------- W transpose + bf16 hi/lo split: [K,N] -> [N,K] ---------
__global__ void wprep_kernel(const float* __restrict__ W) {
    __shared__ float tile[32][33];
    int k0 = blockIdx.x * 32, n0 = blockIdx.y * 32;
    int tx = threadIdx.x, ty = threadIdx.y;  // 32x8
    for (int i = ty; i < 32; i += 8)
        tile[i][tx] = W[(size_t)(k0 + i) * DIM + n0 + tx];
    __syncthreads();
    for (int i = ty; i < 32; i += 8) {
        int n = n0 + i, k = k0 + tx;
        float v = tile[tx][i];
        __nv_bfloat16 h = __float2bfloat16_rn(v);
        float lo = v - __bfloat162float(h);
        g_Whi[(size_t)n * HH + k] = h;
        g_Wlo[(size_t)n * HH + k] = __float2bfloat16_rn(lo);
    }
}

// ---------------- HMMA encode: GEMM(split-bf16) + bias + norm + mask -----
// CTA: 128x128 tile, K in 16 chunks of 64, double-buffered smem.
// Stage layout per buffer (row stride 144B = 9x16B, ldmatrix conflict-free):
//   AHI 0, ALO 18432, BHI 36864, BLO 55296; stage = 73728 B.
#define KC 64
#define NC (HH / KC)        // 16
#define RSTR 144
#define OFF_AHI 0
#define OFF_ALO 18432
#define OFF_BHI 36864
#define OFF_BLO 55296
#define STAGE   73728
#define SMEM_ENC (512 + 2 * STAGE)   // bias @0, stages @512

__global__ __launch_bounds__(256, 1)
void encode_tc_kernel(const float* __restrict__ qh, const float* __restrict__ dh,
                      const float* __restrict__ bias,
                      const int* __restrict__ qmask, const int* __restrict__ dmask)
{
    extern __shared__ __align__(128) char smem[];
    const uint32_t sb = smem_u32(smem);
    const int tid  = threadIdx.x;
    const int wid  = tid >> 5, lane = tid & 31;
    const int wm   = wid >> 2, wn = wid & 3;
    const int mb   = wm * 64, nb = wn * 32;
    const bool isQ = blockIdx.x < (QROWS / 128);
    const float* src = isQ ? qh + (size_t)blockIdx.x * 128 * HH
                           : dh + (size_t)(blockIdx.x - QROWS / 128) * 128 * HH;

    float* biasS = (float*)smem;
    if (tid < DIM) biasS[tid] = bias[tid];

    // per-thread staging coords: row r, half h (k-offset h*32)
    const int r = tid >> 1, h = tid & 1;
    const float* arow = src + (size_t)r * HH + h * 32;
    const uint32_t aDstOff = (uint32_t)(r * RSTR + h * 64);
    const __nv_bfloat16* whrow = g_Whi + (size_t)r * HH + h * 32;
    const __nv_bfloat16* wlrow = g_Wlo + (size_t)r * HH + h * 32;

    // ldmatrix per-lane row offsets
    const uint32_t rowOffA = (uint32_t)((mb + (lane & 15)) * RSTR + (lane >> 4) * 16);
    const uint32_t rowOffB = (uint32_t)((nb + ((lane >> 4) & 1) * 8 + (lane & 7)) * RSTR
                                        + ((lane >> 3) & 1) * 16);

    float acc[4][4][4];
    #pragma unroll
    for (int mf = 0; mf < 4; mf++)
        #pragma unroll
        for (int nf = 0; nf < 4; nf++)
            #pragma unroll
            for (int j = 0; j < 4; j++) acc[mf][nf][j] = 0.0f;

    // ---- prologue: stage chunk 0 into buf 0 ----
    {
        char* bp = smem + 512;
        #pragma unroll
        for (int j = 0; j < 4; j++) {
            float4 f0 = *(const float4*)(arow + j * 8);
            float4 f1 = *(const float4*)(arow + j * 8 + 4);
            uint4 hi = make_uint4(pack_bf2(f0.x, f0.y), pack_bf2(f0.z, f0.w),
                                  pack_bf2(f1.x, f1.y), pack_bf2(f1.z, f1.w));
            float4 r0 = make_float4(f0.x - __bfloat162float(__float2bfloat16_rn(f0.x)),
                                    f0.y - __bfloat162float(__float2bfloat16_rn(f0.y)),
                                    f0.z - __bfloat162float(__float2bfloat16_rn(f0.z)),
                                    f0.w - __bfloat162float(__float2bfloat16_rn(f0.w)));
            float4 r1 = make_float4(f1.x - __bfloat162float(__float2bfloat16_rn(f1.x)),
                                    f1.y - __bfloat162float(__float2bfloat16_rn(f1.y)),
                                    f1.z - __bfloat162float(__float2bfloat16_rn(f1.z)),
                                    f1.w - __bfloat162float(__float2bfloat16_rn(f1.w)));
            uint4 lo = make_uint4(pack_bf2(r0.x, r0.y), pack_bf2(r0.z, r0.w),
                                  pack_bf2(r1.x, r1.y), pack_bf2(r1.z, r1.w));
            *(uint4*)(bp + OFF_AHI + aDstOff + j * 16) = hi;
            *(uint4*)(bp + OFF_ALO + aDstOff + j * 16) = lo;
        }
        uint32_t bsb = sb + 512;
        #pragma unroll
        for (int j = 0; j < 4; j++) {
            cp16(bsb + OFF_BHI + aDstOff + j * 16, whrow + j * 8);
            cp16(bsb + OFF_BLO + aDstOff + j * 16, wlrow + j * 8);
        }
        CP_COMMIT();
    }

    for (int c = 0; c < NC; c++) {
        const int cur = c & 1;
        CP_WAIT0();
        __syncthreads();

        // issue next-chunk loads early (A into regs, B via cp.async)
        float4 fnext[8];
        if (c + 1 < NC) {
            const float* ap = arow + (c + 1) * KC;
            #pragma unroll
            for (int j = 0; j < 8; j++) fnext[j] = *(const float4*)(ap + j * 4);
            uint32_t bsb = sb + 512 + (1 - cur) * STAGE;
            const __nv_bfloat16* wh = whrow + (c + 1) * KC;
            const __nv_bfloat16* wl = wlrow + (c + 1) * KC;
            #pragma unroll
            for (int j = 0; j < 4; j++) {
                cp16(bsb + OFF_BHI + aDstOff + j * 16, wh + j * 8);
                cp16(bsb + OFF_BLO + aDstOff + j * 16, wl + j * 8);
            }
            CP_COMMIT();
        }

        // ---- MMA on current buffer ----
        const uint32_t base = sb + 512 + cur * STAGE;
        #pragma unroll
        for (int ks = 0; ks < 4; ks++) {
            uint32_t ah[4][4], al[4][4], bh[2][4], bl[2][4];
            #pragma unroll
            for (int mf = 0; mf < 4; mf++) {
                uint32_t ao = base + rowOffA + mf * (16 * RSTR) + ks * 32;
                ldmx4(ah[mf], ao + OFF_AHI);
                ldmx4(al[mf], ao + OFF_ALO);
            }
            #pragma unroll
            for (int p = 0; p < 2; p++) {
                uint32_t bo = base + rowOffB + p * (16 * RSTR) + ks * 32;
                ldmx4(bh[p], bo + OFF_BHI);
                ldmx4(bl[p], bo + OFF_BLO);
            }
            #pragma unroll
            for (int mf = 0; mf < 4; mf++)
                #pragma unroll
                for (int nf = 0; nf < 4; nf++) {
                    const uint32_t* bhp = &bh[nf >> 1][(nf & 1) * 2];
                    const uint32_t* blp = &bl[nf >> 1][(nf & 1) * 2];
                    mma16816(acc[mf][nf], ah[mf], bhp);
                    mma16816(acc[mf][nf], al[mf], bhp);
                    mma16816(acc[mf][nf], ah[mf], blp);
                }
        }

        // convert + store next A chunk (loads have long since landed)
        if (c + 1 < NC) {
            char* bp = smem + 512 + (1 - cur) * STAGE;
            #pragma unroll
            for (int j = 0; j < 4; j++) {
                float4 f0 = fnext[2 * j], f1 = fnext[2 * j + 1];
                uint4 hi = make_uint4(pack_bf2(f0.x, f0.y), pack_bf2(f0.z, f0.w),
                                      pack_bf2(f1.x, f1.y), pack_bf2(f1.z, f1.w));
                float4 r0 = make_float4(f0.x - __bfloat162float(__float2bfloat16_rn(f0.x)),
                                        f0.y - __bfloat162float(__float2bfloat16_rn(f0.y)),
                                        f0.z - __bfloat162float(__float2bfloat16_rn(f0.z)),
                                        f0.w - __bfloat162float(__float2bfloat16_rn(f0.w)));
                float4 r1 = make_float4(f1.x - __bfloat162float(__float2bfloat16_rn(f1.x)),
                                        f1.y - __bfloat162float(__float2bfloat16_rn(f1.y)),
                                        f1.z - __bfloat162float(__float2bfloat16_rn(f1.z)),
                                        f1.w - __bfloat162float(__float2bfloat16_rn(f1.w)));
                uint4 lo = make_uint4(pack_bf2(r0.x, r0.y), pack_bf2(r0.z, r0.w),
                                      pack_bf2(r1.x, r1.y), pack_bf2(r1.z, r1.w));
                *(uint4*)(bp + OFF_AHI + aDstOff + j * 16) = hi;
                *(uint4*)(bp + OFF_ALO + aDstOff + j * 16) = lo;
            }
        }
    }

    // ---- epilogue: acc(+bias) -> smem fp32, then per-row norm/mask/write ----
    __syncthreads();
    float* smemf = (float*)(smem + 512);   // [128][132]
    {
        float2 bnf[4];
        #pragma unroll
        for (int nf = 0; nf < 4; nf++) {
            int n0 = nb + nf * 8 + (lane & 3) * 2;
            bnf[nf] = make_float2(biasS[n0], biasS[n0 + 1]);
        }
        #pragma unroll
        for (int mf = 0; mf < 4; mf++) {
            int m0 = mb + mf * 16 + (lane >> 2);
            #pragma unroll
            for (int nf = 0; nf < 4; nf++) {
                int n0 = nb + nf * 8 + (lane & 3) * 2;
                *(float2*)&smemf[m0 * 132 + n0] =
                    make_float2(acc[mf][nf][0] + bnf[nf].x, acc[mf][nf][1] + bnf[nf].y);
                *(float2*)&smemf[(m0 + 8) * 132 + n0] =
                    make_float2(acc[mf][nf][2] + bnf[nf].x, acc[mf][nf][3] + bnf[nf].y);
            }
        }
    }
    __syncthreads();

    if (tid < 128) {
        const float* rowp = &smemf[tid * 132];
        float ss = 0.0f;
        #pragma unroll
        for (int j = 0; j < 128; j++) { float x = rowp[j]; ss += x * x; }
        int grow = blockIdx.x * 128 + tid;
        float m = isQ ? (float)qmask[grow] : (float)dmask[grow - QROWS];
        float sc = m / fmaxf(sqrtf(ss), 1e-12f);

        if (isQ) {
            int b = grow >> 6, qi = grow & 63;
            float* qp = g_qT + (size_t)b * DIM * LQ + qi;
            #pragma unroll
            for (int cc = 0; cc < 128; cc++) qp[cc * LQ] = rowp[cc] * sc;
        } else {
            float* dp = g_d + (size_t)(grow - QROWS) * DIM;
            #pragma unroll
            for (int cc = 0; cc < 128; cc += 4) {
                float4 v = *(const float4*)(rowp + cc);
                *(float4*)(dp + cc) = make_float4(v.x * sc, v.y * sc, v.z * sc, v.w * sc);
            }
        }
    }
}

// ---------------- segment-sum via atomics (one warp per token) -----------
__global__ void pool_accum_kernel(const int* __restrict__ dmask,
                                  const int* __restrict__ labels)
{
    int gwarp = (blockIdx.x * blockDim.x + threadIdx.x) >> 5;
    if (gwarp >= BB * LD) return;
    int b = gwarp / LD, t = gwarp % LD;
    if (dmask[b * LD + t] <= 0) return;
    int lane = threadIdx.x & 31;
    int seg  = labels[b * LD + t] % g_k[b];
    const float4 v = *(const float4*)(g_d + ((size_t)b * LD + t) * DIM + lane * 4);
    float* dst = g_sums + ((size_t)b * MAXK_MAX + seg) * DIM + lane * 4;
    atomicAdd(dst + 0, v.x); atomicAdd(dst + 1, v.y);
    atomicAdd(dst + 2, v.z); atomicAdd(dst + 3, v.w);
    if (lane == 0) atomicAdd(&g_counts[b * MAXK_MAX + seg], 1.0f);
}

// ---------------- mean + L2 normalize pooled clusters --------------------
__global__ void pool_norm_kernel() {
    int b = blockIdx.y, c = blockIdx.x;
    if (c >= g_k[b]) return;
    int t = threadIdx.x;
    float cnt = fmaxf(g_counts[b * MAXK_MAX + c], 1.0f);
    float v = g_sums[((size_t)b * MAXK_MAX + c) * DIM + t] / cnt;
    float ss = v * v;
    #pragma unroll
    for (int off = 16; off; off >>= 1) ss += __shfl_xor_sync(0xffffffffu, ss, off);
    __shared__ float red[4];
    int warp = t >> 5, lane = t & 31;
    if (lane == 0) red[warp] = ss;
    __syncthreads();
    float tot = red[0] + red[1] + red[2] + red[3];
    float inv = 1.0f / fmaxf(sqrtf(tot), 1e-12f);
    g_pool[((size_t)b * MAXK_MAX + c) * DIM + t] = v * inv;
}

// ---------------- sim GEMM + running max ----------------
__global__ __launch_bounds__(256) void score_kernel() {
    const int b  = blockIdx.y;
    const int kb = g_k[b];
    const int c0 = blockIdx.x * 64;
    if (c0 >= kb) return;

    __shared__ float As[64][40];
    __shared__ float Bs[32][64];

    const int tid  = threadIdx.x;
    const int warp = tid >> 5, lane = tid & 31;
    const int rowBase = warp * 8;
    const int colBase = lane * 2;

    float acc[8][2];
    #pragma unroll
    for (int r = 0; r < 8; r++) { acc[r][0] = 0.0f; acc[r][1] = 0.0f; }

    const float* poolB = g_pool + (size_t)b * MAXK_MAX * DIM;
    const float* qT    = g_qT + (size_t)b * DIM * LQ;

    for (int k0 = 0; k0 < DIM; k0 += 32) {
        #pragma unroll
        for (int i = 0; i < 2; i++) {
            int s = tid + 256 * i;
            int r = s >> 3, kk = (s & 7) * 4;
            float4 v = make_float4(0.f, 0.f, 0.f, 0.f);
            if (c0 + r < kb)
                v = *(const float4*)(poolB + (size_t)(c0 + r) * DIM + k0 + kk);
            *(float4*)&As[r][kk] = v;
        }
        #pragma unroll
        for (int i = 0; i < 2; i++) {
            int s = tid + 256 * i;
            int kk = s >> 4, q4 = (s & 15) * 4;
            float4 v = *(const float4*)(qT + (size_t)(k0 + kk) * LQ + q4);
            *(float4*)&Bs[kk][q4] = v;
        }
        __syncthreads();
        #pragma unroll
        for (int kk = 0; kk < 32; kk++) {
            float2 bv = *(const float2*)&Bs[kk][colBase];
            #pragma unroll
            for (int r = 0; r < 8; r++) {
                float a = As[rowBase + r][kk];
                acc[r][0] += a * bv.x;
                acc[r][1] += a * bv.y;
            }
        }
        __syncthreads();
    }

    float m0 = -1e4f, m1 = -1e4f;
    #pragma unroll
    for (int r = 0; r < 8; r++) {
        if (c0 + rowBase + r < kb) {
            m0 = fmaxf(m0, acc[r][0]);
            m1 = fmaxf(m1, acc[r][1]);
        }
    }
    atomicMax(&g_simmax[b * LQ + colBase],     enc_f(m0));
    atomicMax(&g_simmax[b * LQ + colBase + 1], enc_f(m1));
}

// ---------------- finalize ----------------
__global__ void finalize_kernel(const int* __restrict__ qmask, float* __restrict__ out) {
    int b = blockIdx.x, q = threadIdx.x;
    float v = dec_f(g_simmax[b * LQ + q]) * (float)qmask[b * LQ + q];
    #pragma unroll
    for (int off = 16; off; off >>= 1) v += __shfl_xor_sync(0xffffffffu, v, off);
    __shared__ float sm[2];
    int warp = q >> 5, lane = q & 31;
    if (lane == 0) sm[warp] = v;
    __syncthreads();
    if (q == 0) out[b] = sm[0] + sm[1];
}

// ---------------- launch ----------------
extern "C" void kernel_launch(void* const* d_in, const int* in_sizes, int n_in,
                              void* d_out, int out_size)
{
    const float* qh    = (const float*)d_in[0];
    const float* dh    = (const float*)d_in[1];
    const float* Wm    = (const float*)d_in[2];
    const float* bias  = (const float*)d_in[3];
    const int*   qmask = (const int*)d_in[4];
    const int*   dmask = (const int*)d_in[5];
    const int*   labels= (const int*)d_in[6];
    const int*   pfp   = (n_in > 7) ? (const int*)d_in[7] : nullptr;
    float* out = (float*)d_out;

    static int smem_set = 0;
    if (!smem_set) {
        cudaFuncSetAttribute(encode_tc_kernel,
                             cudaFuncAttributeMaxDynamicSharedMemorySize, SMEM_ENC);
        smem_set = 1;
    }

    init_kernel<<<4096, 256>>>();
    k_kernel<<<BB, 256>>>(dmask, pfp);
    {
        dim3 grid(HH / 32, DIM / 32), blk(32, 8);
        wprep_kernel<<<grid, blk>>>(Wm);
    }
    encode_tc_kernel<<<NROWS / 128, 256, SMEM_ENC>>>(qh, dh, bias, qmask, dmask);
    pool_accum_kernel<<<BB * LD / 8, 256>>>(dmask, labels);
    {
        dim3 grid(MAXK_MAX, BB);
        pool_norm_kernel<<<grid, 128>>>();
    }
    {
        dim3 grid((MAXK_MAX + 63) / 64, BB);
        score_kernel<<<grid, 256>>>();
    }
    finalize_kernel<<<BB, 64>>>(qmask, out);
}

// round 4
// speedup vs baseline: 1.5529x; 1.0202x over previous
#include <cuda_runtime.h>
#include <cuda_bf16.h>
#include <math.h>
#include <stdint.h>

#define BB 16
#define LQ 64
#define LD 2048
#define HH 1024
#define DIM 128
#define MAXK_MAX 2049
#define QROWS (BB * LQ)              // 1024
#define NROWS (BB * LQ + BB * LD)    // 33792

// ---------------- scratch (device globals; no allocation) ----------------
__device__ float    g_d[(size_t)BB * LD * DIM];
__device__ float    g_qT[(size_t)BB * DIM * LQ];
__device__ float    g_sums[(size_t)BB * MAXK_MAX * DIM];
__device__ float    g_counts[(size_t)BB * MAXK_MAX];
__device__ float    g_pool[(size_t)BB * MAXK_MAX * DIM];
__device__ int      g_k[BB];
__device__ unsigned g_simmax[BB * LQ];
__device__ __nv_bfloat16 g_Whi[(size_t)DIM * HH];   // W transposed [n][k], hi
__device__ __nv_bfloat16 g_Wlo[(size_t)DIM * HH];   // lo part

// ---------------- helpers ----------------
__device__ __forceinline__ uint32_t smem_u32(const void* p) {
    uint32_t a;
    asm("{ .reg .u64 t; cvta.to.shared.u64 t, %1; cvt.u32.u64 %0, t; }" : "=r"(a) : "l"(p));
    return a;
}
__device__ __forceinline__ void ldmx4(uint32_t* r, uint32_t a) {
    asm volatile("ldmatrix.sync.aligned.m8n8.x4.shared.b16 {%0,%1,%2,%3}, [%4];"
        : "=r"(r[0]), "=r"(r[1]), "=r"(r[2]), "=r"(r[3]) : "r"(a));
}
__device__ __forceinline__ void mma16816(float* d, const uint32_t* a, const uint32_t* b) {
    asm volatile("mma.sync.aligned.m16n8k16.row.col.f32.bf16.bf16.f32 "
        "{%0,%1,%2,%3}, {%4,%5,%6,%7}, {%8,%9}, {%0,%1,%2,%3};"
        : "+f"(d[0]), "+f"(d[1]), "+f"(d[2]), "+f"(d[3])
        : "r"(a[0]), "r"(a[1]), "r"(a[2]), "r"(a[3]), "r"(b[0]), "r"(b[1]));
}
__device__ __forceinline__ void cp16(uint32_t s, const void* g) {
    uint64_t ga = (uint64_t)__cvta_generic_to_global(g);
    asm volatile("cp.async.cg.shared.global [%0], [%1], 16;" :: "r"(s), "l"(ga) : "memory");
}
#define CP_COMMIT() asm volatile("cp.async.commit_group;" ::: "memory")
#define CP_WAIT0()  asm volatile("cp.async.wait_group 0;" ::: "memory")

__device__ __forceinline__ uint32_t pack_bf2(float x, float y) {
    __nv_bfloat162 t(__float2bfloat16_rn(x), __float2bfloat16_rn(y));
    return *(uint32_t*)&t;
}

// ---------------- float <-> orderable-uint for atomicMax ----------------
__device__ __forceinline__ unsigned enc_f(float f) {
    int b = __float_as_int(f);
    return (unsigned)(b ^ ((b >> 31) | 0x80000000));
}
__device__ __forceinline__ float dec_f(unsigned u) {
    int b = (u & 0x80000000u) ? (int)(u ^ 0x80000000u) : ~(int)u;
    return __int_as_float(b);
}

// ---------------- per-batch cluster count ----------------
__global__ void k_kernel(const int* __restrict__ dmask, const int* __restrict__ pfp) {
    int b = blockIdx.x;
    int s = 0;
    for (int i = threadIdx.x; i < LD; i += 256) s += dmask[b * LD + i];
    #pragma unroll
    for (int off = 16; off; off >>= 1) s += __shfl_xor_sync(0xffffffffu, s, off);
    __shared__ int sm[8];
    int warp = threadIdx.x >> 5, lane = threadIdx.x & 31;
    if (lane == 0) sm[warp] = s;
    __syncthreads();
    if (threadIdx.x == 0) {
        int tot = 0;
        #pragma unroll
        for (int w = 0; w < 8; w++) tot += sm[w];
        int pf = pfp ? pfp[0] : 4;
        if (pf < 1) pf = 1;
        int valid = tot < 2 ? 2 : tot;
        g_k[b] = valid / pf + 1;
    }
}

// ---------------- bounded init: zero only live segments ----------------
__global__ void init_kernel() {
    int b = blockIdx.y;
    int k = g_k[b];
    size_t n = (size_t)k * DIM;
    float* sums = g_sums + (size_t)b * MAXK_MAX * DIM;
    size_t i0 = (size_t)blockIdx.x * blockDim.x + threadIdx.x;
    size_t stride = (size_t)gridDim.x * blockDim.x;
    for (size_t j = i0; j < n; j += stride) sums[j] = 0.0f;
    float* cnts = g_counts + (size_t)b * MAXK_MAX;
    for (size_t j = i0; j < (size_t)k; j += stride) cnts[j] = 0.0f;
    if (blockIdx.x == 0) {
        unsigned neg = enc_f(-1e4f);
        for (int j = threadIdx.x; j < LQ; j += blockDim.x) g_simmax[b * LQ + j] = neg;
    }
}

// ---------------- W transpose + bf16 hi/lo split: [K,N] -> [N,K] ---------
__global__ void wprep_kernel(const float* __restrict__ W) {
    __shared__ float tile[32][33];
    int k0 = blockIdx.x * 32, n0 = blockIdx.y * 32;
    int tx = threadIdx.x, ty = threadIdx.y;  // 32x8
    for (int i = ty; i < 32; i += 8)
        tile[i][tx] = W[(size_t)(k0 + i) * DIM + n0 + tx];
    __syncthreads();
    for (int i = ty; i < 32; i += 8) {
        int n = n0 + i, k = k0 + tx;
        float v = tile[tx][i];
        __nv_bfloat16 h = __float2bfloat16_rn(v);
        float lo = v - __bfloat162float(h);
        g_Whi[(size_t)n * HH + k] = h;
        g_Wlo[(size_t)n * HH + k] = __float2bfloat16_rn(lo);
    }
}

// ---------------- HMMA encode: GEMM(split-bf16) + bias + norm + mask -----
#define KC 64
#define NC (HH / KC)        // 16
#define RSTR 144
#define OFF_AHI 0
#define OFF_ALO 18432
#define OFF_BHI 36864
#define OFF_BLO 55296
#define STAGE   73728
#define SMEM_ENC (512 + 2 * STAGE)

__global__ __launch_bounds__(256, 1)
void encode_tc_kernel(const float* __restrict__ qh, const float* __restrict__ dh,
                      const float* __restrict__ bias,
                      const int* __restrict__ qmask, const int* __restrict__ dmask)
{
    extern __shared__ __align__(128) char smem[];
    const uint32_t sb = smem_u32(smem);
    const int tid  = threadIdx.x;
    const int wid  = tid >> 5, lane = tid & 31;
    const int wm   = wid >> 2, wn = wid & 3;
    const int mb   = wm * 64, nb = wn * 32;
    const bool isQ = blockIdx.x < (QROWS / 128);
    const float* src = isQ ? qh + (size_t)blockIdx.x * 128 * HH
                           : dh + (size_t)(blockIdx.x - QROWS / 128) * 128 * HH;

    float* biasS = (float*)smem;
    if (tid < DIM) biasS[tid] = bias[tid];

    const int r = tid >> 1, h = tid & 1;
    const float* arow = src + (size_t)r * HH + h * 32;
    const uint32_t aDstOff = (uint32_t)(r * RSTR + h * 64);
    const __nv_bfloat16* whrow = g_Whi + (size_t)r * HH + h * 32;
    const __nv_bfloat16* wlrow = g_Wlo + (size_t)r * HH + h * 32;

    const uint32_t rowOffA = (uint32_t)((mb + (lane & 15)) * RSTR + (lane >> 4) * 16);
    const uint32_t rowOffB = (uint32_t)((nb + ((lane >> 4) & 1) * 8 + (lane & 7)) * RSTR
                                        + ((lane >> 3) & 1) * 16);

    float acc[4][4][4];
    #pragma unroll
    for (int mf = 0; mf < 4; mf++)
        #pragma unroll
        for (int nf = 0; nf < 4; nf++)
            #pragma unroll
            for (int j = 0; j < 4; j++) acc[mf][nf][j] = 0.0f;

    // ---- prologue: stage chunk 0 into buf 0 ----
    {
        char* bp = smem + 512;
        #pragma unroll
        for (int j = 0; j < 4; j++) {
            float4 f0 = *(const float4*)(arow + j * 8);
            float4 f1 = *(const float4*)(arow + j * 8 + 4);
            uint4 hi = make_uint4(pack_bf2(f0.x, f0.y), pack_bf2(f0.z, f0.w),
                                  pack_bf2(f1.x, f1.y), pack_bf2(f1.z, f1.w));
            float4 r0 = make_float4(f0.x - __bfloat162float(__float2bfloat16_rn(f0.x)),
                                    f0.y - __bfloat162float(__float2bfloat16_rn(f0.y)),
                                    f0.z - __bfloat162float(__float2bfloat16_rn(f0.z)),
                                    f0.w - __bfloat162float(__float2bfloat16_rn(f0.w)));
            float4 r1 = make_float4(f1.x - __bfloat162float(__float2bfloat16_rn(f1.x)),
                                    f1.y - __bfloat162float(__float2bfloat16_rn(f1.y)),
                                    f1.z - __bfloat162float(__float2bfloat16_rn(f1.z)),
                                    f1.w - __bfloat162float(__float2bfloat16_rn(f1.w)));
            uint4 lo = make_uint4(pack_bf2(r0.x, r0.y), pack_bf2(r0.z, r0.w),
                                  pack_bf2(r1.x, r1.y), pack_bf2(r1.z, r1.w));
            *(uint4*)(bp + OFF_AHI + aDstOff + j * 16) = hi;
            *(uint4*)(bp + OFF_ALO + aDstOff + j * 16) = lo;
        }
        uint32_t bsb = sb + 512;
        #pragma unroll
        for (int j = 0; j < 4; j++) {
            cp16(bsb + OFF_BHI + aDstOff + j * 16, whrow + j * 8);
            cp16(bsb + OFF_BLO + aDstOff + j * 16, wlrow + j * 8);
        }
        CP_COMMIT();
    }

    for (int c = 0; c < NC; c++) {
        const int cur = c & 1;
        CP_WAIT0();
        __syncthreads();

        float4 fnext[8];
        if (c + 1 < NC) {
            const float* ap = arow + (c + 1) * KC;
            #pragma unroll
            for (int j = 0; j < 8; j++) fnext[j] = *(const float4*)(ap + j * 4);
            uint32_t bsb = sb + 512 + (1 - cur) * STAGE;
            const __nv_bfloat16* wh = whrow + (c + 1) * KC;
            const __nv_bfloat16* wl = wlrow + (c + 1) * KC;
            #pragma unroll
            for (int j = 0; j < 4; j++) {
                cp16(bsb + OFF_BHI + aDstOff + j * 16, wh + j * 8);
                cp16(bsb + OFF_BLO + aDstOff + j * 16, wl + j * 8);
            }
            CP_COMMIT();
        }

        // ---- MMA on current buffer; term-major to break accumulator RAW ----
        const uint32_t base = sb + 512 + cur * STAGE;
        #pragma unroll
        for (int ks = 0; ks < 4; ks++) {
            uint32_t ah[4][4], al[4][4], bh[2][4], bl[2][4];
            #pragma unroll
            for (int mf = 0; mf < 4; mf++) {
                uint32_t ao = base + rowOffA + mf * (16 * RSTR) + ks * 32;
                ldmx4(ah[mf], ao + OFF_AHI);
                ldmx4(al[mf], ao + OFF_ALO);
            }
            #pragma unroll
            for (int p = 0; p < 2; p++) {
                uint32_t bo = base + rowOffB + p * (16 * RSTR) + ks * 32;
                ldmx4(bh[p], bo + OFF_BHI);
                ldmx4(bl[p], bo + OFF_BLO);
            }
            // term 0: Ahi * Bhi over all 16 fragments (16-deep independence)
            #pragma unroll
            for (int mf = 0; mf < 4; mf++)
                #pragma unroll
                for (int nf = 0; nf < 4; nf++)
                    mma16816(acc[mf][nf], ah[mf], &bh[nf >> 1][(nf & 1) * 2]);
            // term 1: Alo * Bhi
            #pragma unroll
            for (int mf = 0; mf < 4; mf++)
                #pragma unroll
                for (int nf = 0; nf < 4; nf++)
                    mma16816(acc[mf][nf], al[mf], &bh[nf >> 1][(nf & 1) * 2]);
            // term 2: Ahi * Blo
            #pragma unroll
            for (int mf = 0; mf < 4; mf++)
                #pragma unroll
                for (int nf = 0; nf < 4; nf++)
                    mma16816(acc[mf][nf], ah[mf], &bl[nf >> 1][(nf & 1) * 2]);
        }

        if (c + 1 < NC) {
            char* bp = smem + 512 + (1 - cur) * STAGE;
            #pragma unroll
            for (int j = 0; j < 4; j++) {
                float4 f0 = fnext[2 * j], f1 = fnext[2 * j + 1];
                uint4 hi = make_uint4(pack_bf2(f0.x, f0.y), pack_bf2(f0.z, f0.w),
                                      pack_bf2(f1.x, f1.y), pack_bf2(f1.z, f1.w));
                float4 r0 = make_float4(f0.x - __bfloat162float(__float2bfloat16_rn(f0.x)),
                                        f0.y - __bfloat162float(__float2bfloat16_rn(f0.y)),
                                        f0.z - __bfloat162float(__float2bfloat16_rn(f0.z)),
                                        f0.w - __bfloat162float(__float2bfloat16_rn(f0.w)));
                float4 r1 = make_float4(f1.x - __bfloat162float(__float2bfloat16_rn(f1.x)),
                                        f1.y - __bfloat162float(__float2bfloat16_rn(f1.y)),
                                        f1.z - __bfloat162float(__float2bfloat16_rn(f1.z)),
                                        f1.w - __bfloat162float(__float2bfloat16_rn(f1.w)));
                uint4 lo = make_uint4(pack_bf2(r0.x, r0.y), pack_bf2(r0.z, r0.w),
                                      pack_bf2(r1.x, r1.y), pack_bf2(r1.z, r1.w));
                *(uint4*)(bp + OFF_AHI + aDstOff + j * 16) = hi;
                *(uint4*)(bp + OFF_ALO + aDstOff + j * 16) = lo;
            }
        }
    }

    // ---- epilogue ----
    __syncthreads();
    float* smemf = (float*)(smem + 512);   // [128][132]
    {
        float2 bnf[4];
        #pragma unroll
        for (int nf = 0; nf < 4; nf++) {
            int n0 = nb + nf * 8 + (lane & 3) * 2;
            bnf[nf] = make_float2(biasS[n0], biasS[n0 + 1]);
        }
        #pragma unroll
        for (int mf = 0; mf < 4; mf++) {
            int m0 = mb + mf * 16 + (lane >> 2);
            #pragma unroll
            for (int nf = 0; nf < 4; nf++) {
                int n0 = nb + nf * 8 + (lane & 3) * 2;
                *(float2*)&smemf[m0 * 132 + n0] =
                    make_float2(acc[mf][nf][0] + bnf[nf].x, acc[mf][nf][1] + bnf[nf].y);
                *(float2*)&smemf[(m0 + 8) * 132 + n0] =
                    make_float2(acc[mf][nf][2] + bnf[nf].x, acc[mf][nf][3] + bnf[nf].y);
            }
        }
    }
    __syncthreads();

    if (tid < 128) {
        const float* rowp = &smemf[tid * 132];
        float ss = 0.0f;
        #pragma unroll
        for (int j = 0; j < 128; j++) { float x = rowp[j]; ss += x * x; }
        int grow = blockIdx.x * 128 + tid;
        float m = isQ ? (float)qmask[grow] : (float)dmask[grow - QROWS];
        float sc = m / fmaxf(sqrtf(ss), 1e-12f);

        if (isQ) {
            int b = grow >> 6, qi = grow & 63;
            float* qp = g_qT + (size_t)b * DIM * LQ + qi;
            #pragma unroll
            for (int cc = 0; cc < 128; cc++) qp[cc * LQ] = rowp[cc] * sc;
        } else {
            float* dp = g_d + (size_t)(grow - QROWS) * DIM;
            #pragma unroll
            for (int cc = 0; cc < 128; cc += 4) {
                float4 v = *(const float4*)(rowp + cc);
                *(float4*)(dp + cc) = make_float4(v.x * sc, v.y * sc, v.z * sc, v.w * sc);
            }
        }
    }
}

// ---------------- segment-sum via atomics (one warp per token) -----------
__global__ void pool_accum_kernel(const int* __restrict__ dmask,
                                  const int* __restrict__ labels)
{
    int gwarp = (blockIdx.x * blockDim.x + threadIdx.x) >> 5;
    if (gwarp >= BB * LD) return;
    int b = gwarp / LD, t = gwarp % LD;
    if (dmask[b * LD + t] <= 0) return;
    int lane = threadIdx.x & 31;
    int seg  = labels[b * LD + t] % g_k[b];
    const float4 v = *(const float4*)(g_d + ((size_t)b * LD + t) * DIM + lane * 4);
    float* dst = g_sums + ((size_t)b * MAXK_MAX + seg) * DIM + lane * 4;
    atomicAdd(dst + 0, v.x); atomicAdd(dst + 1, v.y);
    atomicAdd(dst + 2, v.z); atomicAdd(dst + 3, v.w);
    if (lane == 0) atomicAdd(&g_counts[b * MAXK_MAX + seg], 1.0f);
}

// ---------------- mean + L2 normalize pooled clusters --------------------
__global__ void pool_norm_kernel() {
    int b = blockIdx.y, c = blockIdx.x;
    if (c >= g_k[b]) return;
    int t = threadIdx.x;
    float cnt = fmaxf(g_counts[b * MAXK_MAX + c], 1.0f);
    float v = g_sums[((size_t)b * MAXK_MAX + c) * DIM + t] / cnt;
    float ss = v * v;
    #pragma unroll
    for (int off = 16; off; off >>= 1) ss += __shfl_xor_sync(0xffffffffu, ss, off);
    __shared__ float red[4];
    int warp = t >> 5, lane = t & 31;
    if (lane == 0) red[warp] = ss;
    __syncthreads();
    float tot = red[0] + red[1] + red[2] + red[3];
    float inv = 1.0f / fmaxf(sqrtf(tot), 1e-12f);
    g_pool[((size_t)b * MAXK_MAX + c) * DIM + t] = v * inv;
}

// ---------------- sim GEMM + running max ----------------
__global__ __launch_bounds__(256) void score_kernel() {
    const int b  = blockIdx.y;
    const int kb = g_k[b];
    const int c0 = blockIdx.x * 64;
    if (c0 >= kb) return;

    __shared__ float As[64][40];
    __shared__ float Bs[32][64];

    const int tid  = threadIdx.x;
    const int warp = tid >> 5, lane = tid & 31;
    const int rowBase = warp * 8;
    const int colBase = lane * 2;

    float acc[8][2];
    #pragma unroll
    for (int r = 0; r < 8; r++) { acc[r][0] = 0.0f; acc[r][1] = 0.0f; }

    const float* poolB = g_pool + (size_t)b * MAXK_MAX * DIM;
    const float* qT    = g_qT + (size_t)b * DIM * LQ;

    for (int k0 = 0; k0 < DIM; k0 += 32) {
        #pragma unroll
        for (int i = 0; i < 2; i++) {
            int s = tid + 256 * i;
            int r = s >> 3, kk = (s & 7) * 4;
            float4 v = make_float4(0.f, 0.f, 0.f, 0.f);
            if (c0 + r < kb)
                v = *(const float4*)(poolB + (size_t)(c0 + r) * DIM + k0 + kk);
            *(float4*)&As[r][kk] = v;
        }
        #pragma unroll
        for (int i = 0; i < 2; i++) {
            int s = tid + 256 * i;
            int kk = s >> 4, q4 = (s & 15) * 4;
            float4 v = *(const float4*)(qT + (size_t)(k0 + kk) * LQ + q4);
            *(float4*)&Bs[kk][q4] = v;
        }
        __syncthreads();
        #pragma unroll
        for (int kk = 0; kk < 32; kk++) {
            float2 bv = *(const float2*)&Bs[kk][colBase];
            #pragma unroll
            for (int r = 0; r < 8; r++) {
                float a = As[rowBase + r][kk];
                acc[r][0] += a * bv.x;
                acc[r][1] += a * bv.y;
            }
        }
        __syncthreads();
    }

    float m0 = -1e4f, m1 = -1e4f;
    #pragma unroll
    for (int r = 0; r < 8; r++) {
        if (c0 + rowBase + r < kb) {
            m0 = fmaxf(m0, acc[r][0]);
            m1 = fmaxf(m1, acc[r][1]);
        }
    }
    atomicMax(&g_simmax[b * LQ + colBase],     enc_f(m0));
    atomicMax(&g_simmax[b * LQ + colBase + 1], enc_f(m1));
}

// ---------------- finalize ----------------
__global__ void finalize_kernel(const int* __restrict__ qmask, float* __restrict__ out) {
    int b = blockIdx.x, q = threadIdx.x;
    float v = dec_f(g_simmax[b * LQ + q]) * (float)qmask[b * LQ + q];
    #pragma unroll
    for (int off = 16; off; off >>= 1) v += __shfl_xor_sync(0xffffffffu, v, off);
    __shared__ float sm[2];
    int warp = q >> 5, lane = q & 31;
    if (lane == 0) sm[warp] = v;
    __syncthreads();
    if (q == 0) out[b] = sm[0] + sm[1];
}

// ---------------- launch ----------------
extern "C" void kernel_launch(void* const* d_in, const int* in_sizes, int n_in,
                              void* d_out, int out_size)
{
    const float* qh    = (const float*)d_in[0];
    const float* dh    = (const float*)d_in[1];
    const float* Wm    = (const float*)d_in[2];
    const float* bias  = (const float*)d_in[3];
    const int*   qmask = (const int*)d_in[4];
    const int*   dmask = (const int*)d_in[5];
    const int*   labels= (const int*)d_in[6];
    const int*   pfp   = (n_in > 7) ? (const int*)d_in[7] : nullptr;
    float* out = (float*)d_out;

    static int smem_set = 0;
    if (!smem_set) {
        cudaFuncSetAttribute(encode_tc_kernel,
                             cudaFuncAttributeMaxDynamicSharedMemorySize, SMEM_ENC);
        smem_set = 1;
    }

    k_kernel<<<BB, 256>>>(dmask, pfp);
    {
        dim3 grid(24, BB);
        init_kernel<<<grid, 256>>>();
    }
    {
        dim3 grid(HH / 32, DIM / 32), blk(32, 8);
        wprep_kernel<<<grid, blk>>>(Wm);
    }
    encode_tc_kernel<<<NROWS / 128, 256, SMEM_ENC>>>(qh, dh, bias, qmask, dmask);
    pool_accum_kernel<<<BB * LD / 8, 256>>>(dmask, labels);
    {
        dim3 grid(MAXK_MAX, BB);
        pool_norm_kernel<<<grid, 128>>>();
    }
    {
        dim3 grid((MAXK_MAX + 63) / 64, BB);
        score_kernel<<<grid, 256>>>();
    }
    finalize_kernel<<<BB, 64>>>(qmask, out);
}

// round 5
// speedup vs baseline: 1.6412x; 1.0569x over previous
#include <cuda_runtime.h>
#include <cuda_bf16.h>
#include <math.h>
#include <stdint.h>

#define BB 16
#define LQ 64
#define LD 2048
#define HH 1024
#define DIM 128
#define MAXK_MAX 2049
#define QROWS (BB * LQ)              // 1024
#define NROWS (BB * LQ + BB * LD)    // 33792

// ---------------- scratch (device globals; no allocation) ----------------
__device__ float    g_d[(size_t)BB * LD * DIM];
__device__ float    g_qT[(size_t)BB * DIM * LQ];
__device__ float    g_sums[(size_t)BB * MAXK_MAX * DIM];
__device__ float    g_counts[(size_t)BB * MAXK_MAX];
__device__ float    g_pool[(size_t)BB * MAXK_MAX * DIM];
__device__ int      g_k[BB];
__device__ unsigned g_simmax[BB * LQ];
__device__ __nv_bfloat16 g_Whi[(size_t)DIM * HH];   // W transposed [n][k], hi
__device__ __nv_bfloat16 g_Wlo[(size_t)DIM * HH];   // lo part

// ---------------- helpers ----------------
__device__ __forceinline__ uint32_t smem_u32(const void* p) {
    uint32_t a;
    asm("{ .reg .u64 t; cvta.to.shared.u64 t, %1; cvt.u32.u64 %0, t; }" : "=r"(a) : "l"(p));
    return a;
}
__device__ __forceinline__ void ldmx4(uint32_t* r, uint32_t a) {
    asm volatile("ldmatrix.sync.aligned.m8n8.x4.shared.b16 {%0,%1,%2,%3}, [%4];"
        : "=r"(r[0]), "=r"(r[1]), "=r"(r[2]), "=r"(r[3]) : "r"(a));
}
__device__ __forceinline__ void mma16816(float* d, const uint32_t* a, const uint32_t* b) {
    asm volatile("mma.sync.aligned.m16n8k16.row.col.f32.bf16.bf16.f32 "
        "{%0,%1,%2,%3}, {%4,%5,%6,%7}, {%8,%9}, {%0,%1,%2,%3};"
        : "+f"(d[0]), "+f"(d[1]), "+f"(d[2]), "+f"(d[3])
        : "r"(a[0]), "r"(a[1]), "r"(a[2]), "r"(a[3]), "r"(b[0]), "r"(b[1]));
}
__device__ __forceinline__ void cp16(uint32_t s, const void* g) {
    uint64_t ga = (uint64_t)__cvta_generic_to_global(g);
    asm volatile("cp.async.cg.shared.global [%0], [%1], 16;" :: "r"(s), "l"(ga) : "memory");
}
#define CP_COMMIT() asm volatile("cp.async.commit_group;" ::: "memory")
#define CP_WAIT0()  asm volatile("cp.async.wait_group 0;" ::: "memory")

__device__ __forceinline__ uint32_t pack_bf2(float x, float y) {
    __nv_bfloat162 t(__float2bfloat16_rn(x), __float2bfloat16_rn(y));
    return *(uint32_t*)&t;
}

// ---------------- float <-> orderable-uint for atomicMax ----------------
__device__ __forceinline__ unsigned enc_f(float f) {
    int b = __float_as_int(f);
    return (unsigned)(b ^ ((b >> 31) | 0x80000000));
}
__device__ __forceinline__ float dec_f(unsigned u) {
    int b = (u & 0x80000000u) ? (int)(u ^ 0x80000000u) : ~(int)u;
    return __int_as_float(b);
}

// ---------------- per-batch cluster count ----------------
__global__ void k_kernel(const int* __restrict__ dmask, const int* __restrict__ pfp) {
    int b = blockIdx.x;
    int s = 0;
    for (int i = threadIdx.x; i < LD; i += 256) s += dmask[b * LD + i];
    #pragma unroll
    for (int off = 16; off; off >>= 1) s += __shfl_xor_sync(0xffffffffu, s, off);
    __shared__ int sm[8];
    int warp = threadIdx.x >> 5, lane = threadIdx.x & 31;
    if (lane == 0) sm[warp] = s;
    __syncthreads();
    if (threadIdx.x == 0) {
        int tot = 0;
        #pragma unroll
        for (int w = 0; w < 8; w++) tot += sm[w];
        int pf = pfp ? pfp[0] : 4;
        if (pf < 1) pf = 1;
        int valid = tot < 2 ? 2 : tot;
        g_k[b] = valid / pf + 1;
    }
}

// ---------------- bounded init: zero only live segments ----------------
__global__ void init_kernel() {
    int b = blockIdx.y;
    int k = g_k[b];
    size_t n = (size_t)k * DIM;
    float* sums = g_sums + (size_t)b * MAXK_MAX * DIM;
    size_t i0 = (size_t)blockIdx.x * blockDim.x + threadIdx.x;
    size_t stride = (size_t)gridDim.x * blockDim.x;
    for (size_t j = i0; j < n; j += stride) sums[j] = 0.0f;
    float* cnts = g_counts + (size_t)b * MAXK_MAX;
    for (size_t j = i0; j < (size_t)k; j += stride) cnts[j] = 0.0f;
    if (blockIdx.x == 0) {
        unsigned neg = enc_f(-1e4f);
        for (int j = threadIdx.x; j < LQ; j += blockDim.x) g_simmax[b * LQ + j] = neg;
    }
}

// ---------------- W transpose + bf16 hi/lo split: [K,N] -> [N,K] ---------
__global__ void wprep_kernel(const float* __restrict__ W) {
    __shared__ float tile[32][33];
    int k0 = blockIdx.x * 32, n0 = blockIdx.y * 32;
    int tx = threadIdx.x, ty = threadIdx.y;  // 32x8
    for (int i = ty; i < 32; i += 8)
        tile[i][tx] = W[(size_t)(k0 + i) * DIM + n0 + tx];
    __syncthreads();
    for (int i = ty; i < 32; i += 8) {
        int n = n0 + i, k = k0 + tx;
        float v = tile[tx][i];
        __nv_bfloat16 h = __float2bfloat16_rn(v);
        float lo = v - __bfloat162float(h);
        g_Whi[(size_t)n * HH + k] = h;
        g_Wlo[(size_t)n * HH + k] = __float2bfloat16_rn(lo);
    }
}

// ---------------- HMMA encode: GEMM(split-bf16) + bias + norm + mask -----
// 512 threads, 16 warps (4x4), warp tile 32x32, CTA tile 128x128.
#define KC 64
#define NC (HH / KC)        // 16
#define RSTR 144
#define OFF_AHI 0
#define OFF_ALO 18432
#define OFF_BHI 36864
#define OFF_BLO 55296
#define STAGE   73728
#define SMEM_ENC (512 + 2 * STAGE)

__global__ __launch_bounds__(512, 1)
void encode_tc_kernel(const float* __restrict__ qh, const float* __restrict__ dh,
                      const float* __restrict__ bias,
                      const int* __restrict__ qmask, const int* __restrict__ dmask)
{
    extern __shared__ __align__(128) char smem[];
    const uint32_t sb = smem_u32(smem);
    const int tid  = threadIdx.x;
    const int wid  = tid >> 5, lane = tid & 31;
    const int wm   = wid >> 2, wn = wid & 3;
    const int mb   = wm * 32, nb = wn * 32;
    const bool isQ = blockIdx.x < (QROWS / 128);
    const float* src = isQ ? qh + (size_t)blockIdx.x * 128 * HH
                           : dh + (size_t)(blockIdx.x - QROWS / 128) * 128 * HH;

    float* biasS = (float*)smem;
    if (tid < DIM) biasS[tid] = bias[tid];

    // staging coords: each thread owns a 16-float quarter-row per chunk
    const int r = tid >> 2, q = tid & 3;
    const float* arow = src + (size_t)r * HH + q * 16;
    const uint32_t aDstOff = (uint32_t)(r * RSTR + q * 32);
    const __nv_bfloat16* whrow = g_Whi + (size_t)r * HH + q * 16;
    const __nv_bfloat16* wlrow = g_Wlo + (size_t)r * HH + q * 16;

    const uint32_t rowOffA = (uint32_t)((mb + (lane & 15)) * RSTR + (lane >> 4) * 16);
    const uint32_t rowOffB = (uint32_t)((nb + ((lane >> 4) & 1) * 8 + (lane & 7)) * RSTR
                                        + ((lane >> 3) & 1) * 16);

    float acc[2][4][4];
    #pragma unroll
    for (int mf = 0; mf < 2; mf++)
        #pragma unroll
        for (int nf = 0; nf < 4; nf++)
            #pragma unroll
            for (int j = 0; j < 4; j++) acc[mf][nf][j] = 0.0f;

    // ---- staging helper: convert 16 floats -> hi/lo smem ----
    // ---- prologue: stage chunk 0 into buf 0 ----
    {
        char* bp = smem + 512;
        #pragma unroll
        for (int j = 0; j < 2; j++) {
            float4 f0 = *(const float4*)(arow + j * 8);
            float4 f1 = *(const float4*)(arow + j * 8 + 4);
            uint4 hi = make_uint4(pack_bf2(f0.x, f0.y), pack_bf2(f0.z, f0.w),
                                  pack_bf2(f1.x, f1.y), pack_bf2(f1.z, f1.w));
            float4 r0 = make_float4(f0.x - __bfloat162float(__float2bfloat16_rn(f0.x)),
                                    f0.y - __bfloat162float(__float2bfloat16_rn(f0.y)),
                                    f0.z - __bfloat162float(__float2bfloat16_rn(f0.z)),
                                    f0.w - __bfloat162float(__float2bfloat16_rn(f0.w)));
            float4 r1 = make_float4(f1.x - __bfloat162float(__float2bfloat16_rn(f1.x)),
                                    f1.y - __bfloat162float(__float2bfloat16_rn(f1.y)),
                                    f1.z - __bfloat162float(__float2bfloat16_rn(f1.z)),
                                    f1.w - __bfloat162float(__float2bfloat16_rn(f1.w)));
            uint4 lo = make_uint4(pack_bf2(r0.x, r0.y), pack_bf2(r0.z, r0.w),
                                  pack_bf2(r1.x, r1.y), pack_bf2(r1.z, r1.w));
            *(uint4*)(bp + OFF_AHI + aDstOff + j * 16) = hi;
            *(uint4*)(bp + OFF_ALO + aDstOff + j * 16) = lo;
        }
        uint32_t bsb = sb + 512;
        #pragma unroll
        for (int j = 0; j < 2; j++) {
            cp16(bsb + OFF_BHI + aDstOff + j * 16, whrow + j * 8);
            cp16(bsb + OFF_BLO + aDstOff + j * 16, wlrow + j * 8);
        }
        CP_COMMIT();
    }

    for (int c = 0; c < NC; c++) {
        const int cur = c & 1;
        CP_WAIT0();
        __syncthreads();

        float4 fnext[4];
        if (c + 1 < NC) {
            const float* ap = arow + (c + 1) * KC;
            #pragma unroll
            for (int j = 0; j < 4; j++) fnext[j] = *(const float4*)(ap + j * 4);
            uint32_t bsb = sb + 512 + (1 - cur) * STAGE;
            const __nv_bfloat16* wh = whrow + (c + 1) * KC;
            const __nv_bfloat16* wl = wlrow + (c + 1) * KC;
            #pragma unroll
            for (int j = 0; j < 2; j++) {
                cp16(bsb + OFF_BHI + aDstOff + j * 16, wh + j * 8);
                cp16(bsb + OFF_BLO + aDstOff + j * 16, wl + j * 8);
            }
            CP_COMMIT();
        }

        // ---- MMA on current buffer ----
        const uint32_t base = sb + 512 + cur * STAGE;
        #pragma unroll
        for (int ks = 0; ks < 4; ks++) {
            uint32_t ah[2][4], al[2][4], bh[2][4], bl[2][4];
            #pragma unroll
            for (int mf = 0; mf < 2; mf++) {
                uint32_t ao = base + rowOffA + mf * (16 * RSTR) + ks * 32;
                ldmx4(ah[mf], ao + OFF_AHI);
                ldmx4(al[mf], ao + OFF_ALO);
            }
            #pragma unroll
            for (int p = 0; p < 2; p++) {
                uint32_t bo = base + rowOffB + p * (16 * RSTR) + ks * 32;
                ldmx4(bh[p], bo + OFF_BHI);
                ldmx4(bl[p], bo + OFF_BLO);
            }
            #pragma unroll
            for (int mf = 0; mf < 2; mf++)
                #pragma unroll
                for (int nf = 0; nf < 4; nf++)
                    mma16816(acc[mf][nf], ah[mf], &bh[nf >> 1][(nf & 1) * 2]);
            #pragma unroll
            for (int mf = 0; mf < 2; mf++)
                #pragma unroll
                for (int nf = 0; nf < 4; nf++)
                    mma16816(acc[mf][nf], al[mf], &bh[nf >> 1][(nf & 1) * 2]);
            #pragma unroll
            for (int mf = 0; mf < 2; mf++)
                #pragma unroll
                for (int nf = 0; nf < 4; nf++)
                    mma16816(acc[mf][nf], ah[mf], &bl[nf >> 1][(nf & 1) * 2]);
        }

        if (c + 1 < NC) {
            char* bp = smem + 512 + (1 - cur) * STAGE;
            #pragma unroll
            for (int j = 0; j < 2; j++) {
                float4 f0 = fnext[2 * j], f1 = fnext[2 * j + 1];
                uint4 hi = make_uint4(pack_bf2(f0.x, f0.y), pack_bf2(f0.z, f0.w),
                                      pack_bf2(f1.x, f1.y), pack_bf2(f1.z, f1.w));
                float4 r0 = make_float4(f0.x - __bfloat162float(__float2bfloat16_rn(f0.x)),
                                        f0.y - __bfloat162float(__float2bfloat16_rn(f0.y)),
                                        f0.z - __bfloat162float(__float2bfloat16_rn(f0.z)),
                                        f0.w - __bfloat162float(__float2bfloat16_rn(f0.w)));
                float4 r1 = make_float4(f1.x - __bfloat162float(__float2bfloat16_rn(f1.x)),
                                        f1.y - __bfloat162float(__float2bfloat16_rn(f1.y)),
                                        f1.z - __bfloat162float(__float2bfloat16_rn(f1.z)),
                                        f1.w - __bfloat162float(__float2bfloat16_rn(f1.w)));
                uint4 lo = make_uint4(pack_bf2(r0.x, r0.y), pack_bf2(r0.z, r0.w),
                                      pack_bf2(r1.x, r1.y), pack_bf2(r1.z, r1.w));
                *(uint4*)(bp + OFF_AHI + aDstOff + j * 16) = hi;
                *(uint4*)(bp + OFF_ALO + aDstOff + j * 16) = lo;
            }
        }
    }

    // ---- epilogue ----
    __syncthreads();
    float* smemf = (float*)(smem + 512);   // [128][132]
    {
        float2 bnf[4];
        #pragma unroll
        for (int nf = 0; nf < 4; nf++) {
            int n0 = nb + nf * 8 + (lane & 3) * 2;
            bnf[nf] = make_float2(biasS[n0], biasS[n0 + 1]);
        }
        #pragma unroll
        for (int mf = 0; mf < 2; mf++) {
            int m0 = mb + mf * 16 + (lane >> 2);
            #pragma unroll
            for (int nf = 0; nf < 4; nf++) {
                int n0 = nb + nf * 8 + (lane & 3) * 2;
                *(float2*)&smemf[m0 * 132 + n0] =
                    make_float2(acc[mf][nf][0] + bnf[nf].x, acc[mf][nf][1] + bnf[nf].y);
                *(float2*)&smemf[(m0 + 8) * 132 + n0] =
                    make_float2(acc[mf][nf][2] + bnf[nf].x, acc[mf][nf][3] + bnf[nf].y);
            }
        }
    }
    __syncthreads();

    // 4 threads per row: each sums 32 cols, reduce in quad
    {
        int row = tid >> 2, qq = tid & 3;
        const float* rowp = &smemf[row * 132];
        float ss = 0.0f;
        #pragma unroll
        for (int j = 0; j < 32; j++) { float x = rowp[qq * 32 + j]; ss += x * x; }
        ss += __shfl_xor_sync(0xffffffffu, ss, 1);
        ss += __shfl_xor_sync(0xffffffffu, ss, 2);
        int grow = blockIdx.x * 128 + row;
        float m = isQ ? (float)qmask[grow] : (float)dmask[grow - QROWS];
        float sc = m / fmaxf(sqrtf(ss), 1e-12f);

        if (isQ) {
            int b = grow >> 6, qi = grow & 63;
            float* qp = g_qT + (size_t)b * DIM * LQ + qi;
            #pragma unroll
            for (int cc = 0; cc < 32; cc++) qp[(qq * 32 + cc) * LQ] = rowp[qq * 32 + cc] * sc;
        } else {
            float* dp = g_d + (size_t)(grow - QROWS) * DIM;
            #pragma unroll
            for (int cc = 0; cc < 32; cc += 4) {
                float4 v = *(const float4*)(rowp + qq * 32 + cc);
                *(float4*)(dp + qq * 32 + cc) = make_float4(v.x * sc, v.y * sc, v.z * sc, v.w * sc);
            }
        }
    }
}

// ---------------- segment-sum via atomics (one warp per token) -----------
__global__ void pool_accum_kernel(const int* __restrict__ dmask,
                                  const int* __restrict__ labels)
{
    int gwarp = (blockIdx.x * blockDim.x + threadIdx.x) >> 5;
    if (gwarp >= BB * LD) return;
    int b = gwarp / LD, t = gwarp % LD;
    if (dmask[b * LD + t] <= 0) return;
    int lane = threadIdx.x & 31;
    int seg  = labels[b * LD + t] % g_k[b];
    const float4 v = *(const float4*)(g_d + ((size_t)b * LD + t) * DIM + lane * 4);
    float* dst = g_sums + ((size_t)b * MAXK_MAX + seg) * DIM + lane * 4;
    atomicAdd(dst + 0, v.x); atomicAdd(dst + 1, v.y);
    atomicAdd(dst + 2, v.z); atomicAdd(dst + 3, v.w);
    if (lane == 0) atomicAdd(&g_counts[b * MAXK_MAX + seg], 1.0f);
}

// ---------------- mean + L2 normalize pooled clusters --------------------
__global__ void pool_norm_kernel() {
    int b = blockIdx.y, c = blockIdx.x;
    if (c >= g_k[b]) return;
    int t = threadIdx.x;
    float cnt = fmaxf(g_counts[b * MAXK_MAX + c], 1.0f);
    float v = g_sums[((size_t)b * MAXK_MAX + c) * DIM + t] / cnt;
    float ss = v * v;
    #pragma unroll
    for (int off = 16; off; off >>= 1) ss += __shfl_xor_sync(0xffffffffu, ss, off);
    __shared__ float red[4];
    int warp = t >> 5, lane = t & 31;
    if (lane == 0) red[warp] = ss;
    __syncthreads();
    float tot = red[0] + red[1] + red[2] + red[3];
    float inv = 1.0f / fmaxf(sqrtf(tot), 1e-12f);
    g_pool[((size_t)b * MAXK_MAX + c) * DIM + t] = v * inv;
}

// ---------------- sim GEMM + running max ----------------
__global__ __launch_bounds__(256) void score_kernel() {
    const int b  = blockIdx.y;
    const int kb = g_k[b];
    const int c0 = blockIdx.x * 64;
    if (c0 >= kb) return;

    __shared__ float As[64][40];
    __shared__ float Bs[32][64];

    const int tid  = threadIdx.x;
    const int warp = tid >> 5, lane = tid & 31;
    const int rowBase = warp * 8;
    const int colBase = lane * 2;

    float acc[8][2];
    #pragma unroll
    for (int r = 0; r < 8; r++) { acc[r][0] = 0.0f; acc[r][1] = 0.0f; }

    const float* poolB = g_pool + (size_t)b * MAXK_MAX * DIM;
    const float* qT    = g_qT + (size_t)b * DIM * LQ;

    for (int k0 = 0; k0 < DIM; k0 += 32) {
        #pragma unroll
        for (int i = 0; i < 2; i++) {
            int s = tid + 256 * i;
            int r = s >> 3, kk = (s & 7) * 4;
            float4 v = make_float4(0.f, 0.f, 0.f, 0.f);
            if (c0 + r < kb)
                v = *(const float4*)(poolB + (size_t)(c0 + r) * DIM + k0 + kk);
            *(float4*)&As[r][kk] = v;
        }
        #pragma unroll
        for (int i = 0; i < 2; i++) {
            int s = tid + 256 * i;
            int kk = s >> 4, q4 = (s & 15) * 4;
            float4 v = *(const float4*)(qT + (size_t)(k0 + kk) * LQ + q4);
            *(float4*)&Bs[kk][q4] = v;
        }
        __syncthreads();
        #pragma unroll
        for (int kk = 0; kk < 32; kk++) {
            float2 bv = *(const float2*)&Bs[kk][colBase];
            #pragma unroll
            for (int r = 0; r < 8; r++) {
                float a = As[rowBase + r][kk];
                acc[r][0] += a * bv.x;
                acc[r][1] += a * bv.y;
            }
        }
        __syncthreads();
    }

    float m0 = -1e4f, m1 = -1e4f;
    #pragma unroll
    for (int r = 0; r < 8; r++) {
        if (c0 + rowBase + r < kb) {
            m0 = fmaxf(m0, acc[r][0]);
            m1 = fmaxf(m1, acc[r][1]);
        }
    }
    atomicMax(&g_simmax[b * LQ + colBase],     enc_f(m0));
    atomicMax(&g_simmax[b * LQ + colBase + 1], enc_f(m1));
}

// ---------------- finalize ----------------
__global__ void finalize_kernel(const int* __restrict__ qmask, float* __restrict__ out) {
    int b = blockIdx.x, q = threadIdx.x;
    float v = dec_f(g_simmax[b * LQ + q]) * (float)qmask[b * LQ + q];
    #pragma unroll
    for (int off = 16; off; off >>= 1) v += __shfl_xor_sync(0xffffffffu, v, off);
    __shared__ float sm[2];
    int warp = q >> 5, lane = q & 31;
    if (lane == 0) sm[warp] = v;
    __syncthreads();
    if (q == 0) out[b] = sm[0] + sm[1];
}

// ---------------- launch ----------------
extern "C" void kernel_launch(void* const* d_in, const int* in_sizes, int n_in,
                              void* d_out, int out_size)
{
    const float* qh    = (const float*)d_in[0];
    const float* dh    = (const float*)d_in[1];
    const float* Wm    = (const float*)d_in[2];
    const float* bias  = (const float*)d_in[3];
    const int*   qmask = (const int*)d_in[4];
    const int*   dmask = (const int*)d_in[5];
    const int*   labels= (const int*)d_in[6];
    const int*   pfp   = (n_in > 7) ? (const int*)d_in[7] : nullptr;
    float* out = (float*)d_out;

    static int smem_set = 0;
    if (!smem_set) {
        cudaFuncSetAttribute(encode_tc_kernel,
                             cudaFuncAttributeMaxDynamicSharedMemorySize, SMEM_ENC);
        smem_set = 1;
    }

    k_kernel<<<BB, 256>>>(dmask, pfp);
    {
        dim3 grid(24, BB);
        init_kernel<<<grid, 256>>>();
    }
    {
        dim3 grid(HH / 32, DIM / 32), blk(32, 8);
        wprep_kernel<<<grid, blk>>>(Wm);
    }
    encode_tc_kernel<<<NROWS / 128, 512, SMEM_ENC>>>(qh, dh, bias, qmask, dmask);
    pool_accum_kernel<<<BB * LD / 8, 256>>>(dmask, labels);
    {
        dim3 grid(MAXK_MAX, BB);
        pool_norm_kernel<<<grid, 128>>>();
    }
    {
        dim3 grid((MAXK_MAX + 63) / 64, BB);
        score_kernel<<<grid, 256>>>();
    }
    finalize_kernel<<<BB, 64>>>(qmask, out);
}

// round 6
// speedup vs baseline: 1.8021x; 1.0980x over previous
#include <cuda_runtime.h>
#include <cuda_bf16.h>
#include <math.h>
#include <stdint.h>

#define BB 16
#define LQ 64
#define LD 2048
#define HH 1024
#define DIM 128
#define MAXK_MAX 2049
#define QROWS (BB * LQ)              // 1024
#define NROWS (BB * LQ + BB * LD)    // 33792

// ---------------- scratch (device globals; no allocation) ----------------
__device__ float    g_d[(size_t)BB * LD * DIM];
__device__ float    g_qT[(size_t)BB * DIM * LQ];
__device__ float    g_sums[(size_t)BB * MAXK_MAX * DIM];
__device__ float    g_counts[(size_t)BB * MAXK_MAX];
__device__ float    g_pool[(size_t)BB * MAXK_MAX * DIM];
__device__ int      g_k[BB];
__device__ unsigned g_simmax[BB * LQ];
__device__ __nv_bfloat16 g_Whi[(size_t)DIM * HH];   // W transposed [n][k], hi
__device__ __nv_bfloat16 g_Wlo[(size_t)DIM * HH];   // lo part

// ---------------- helpers ----------------
__device__ __forceinline__ uint32_t smem_u32(const void* p) {
    uint32_t a;
    asm("{ .reg .u64 t; cvta.to.shared.u64 t, %1; cvt.u32.u64 %0, t; }" : "=r"(a) : "l"(p));
    return a;
}
__device__ __forceinline__ void ldmx4(uint32_t* r, uint32_t a) {
    asm volatile("ldmatrix.sync.aligned.m8n8.x4.shared.b16 {%0,%1,%2,%3}, [%4];"
        : "=r"(r[0]), "=r"(r[1]), "=r"(r[2]), "=r"(r[3]) : "r"(a));
}
__device__ __forceinline__ void mma16816(float* d, const uint32_t* a, const uint32_t* b) {
    asm volatile("mma.sync.aligned.m16n8k16.row.col.f32.bf16.bf16.f32 "
        "{%0,%1,%2,%3}, {%4,%5,%6,%7}, {%8,%9}, {%0,%1,%2,%3};"
        : "+f"(d[0]), "+f"(d[1]), "+f"(d[2]), "+f"(d[3])
        : "r"(a[0]), "r"(a[1]), "r"(a[2]), "r"(a[3]), "r"(b[0]), "r"(b[1]));
}
__device__ __forceinline__ void cp16(uint32_t s, const void* g) {
    uint64_t ga = (uint64_t)__cvta_generic_to_global(g);
    asm volatile("cp.async.cg.shared.global [%0], [%1], 16;" :: "r"(s), "l"(ga) : "memory");
}
#define CP_COMMIT() asm volatile("cp.async.commit_group;" ::: "memory")
#define CP_WAITN(n) asm volatile("cp.async.wait_group %0;" :: "n"(n) : "memory")

__device__ __forceinline__ uint32_t pack_bf2(float x, float y) {
    __nv_bfloat162 t(__float2bfloat16_rn(x), __float2bfloat16_rn(y));
    return *(uint32_t*)&t;
}

// ---------------- float <-> orderable-uint for atomicMax ----------------
__device__ __forceinline__ unsigned enc_f(float f) {
    int b = __float_as_int(f);
    return (unsigned)(b ^ ((b >> 31) | 0x80000000));
}
__device__ __forceinline__ float dec_f(unsigned u) {
    int b = (u & 0x80000000u) ? (int)(u ^ 0x80000000u) : ~(int)u;
    return __int_as_float(b);
}

// ---------------- per-batch cluster count ----------------
__global__ void k_kernel(const int* __restrict__ dmask, const int* __restrict__ pfp) {
    int b = blockIdx.x;
    int s = 0;
    for (int i = threadIdx.x; i < LD; i += 256) s += dmask[b * LD + i];
    #pragma unroll
    for (int off = 16; off; off >>= 1) s += __shfl_xor_sync(0xffffffffu, s, off);
    __shared__ int sm[8];
    int warp = threadIdx.x >> 5, lane = threadIdx.x & 31;
    if (lane == 0) sm[warp] = s;
    __syncthreads();
    if (threadIdx.x == 0) {
        int tot = 0;
        #pragma unroll
        for (int w = 0; w < 8; w++) tot += sm[w];
        int pf = pfp ? pfp[0] : 4;
        if (pf < 1) pf = 1;
        int valid = tot < 2 ? 2 : tot;
        g_k[b] = valid / pf + 1;
    }
}

// ---------------- bounded init ----------------
__global__ void init_kernel() {
    int b = blockIdx.y;
    int k = g_k[b];
    size_t n = (size_t)k * DIM;
    float* sums = g_sums + (size_t)b * MAXK_MAX * DIM;
    size_t i0 = (size_t)blockIdx.x * blockDim.x + threadIdx.x;
    size_t stride = (size_t)gridDim.x * blockDim.x;
    for (size_t j = i0; j < n; j += stride) sums[j] = 0.0f;
    float* cnts = g_counts + (size_t)b * MAXK_MAX;
    for (size_t j = i0; j < (size_t)k; j += stride) cnts[j] = 0.0f;
    if (blockIdx.x == 0) {
        unsigned neg = enc_f(-1e4f);
        for (int j = threadIdx.x; j < LQ; j += blockDim.x) g_simmax[b * LQ + j] = neg;
    }
}

// ---------------- W transpose + bf16 hi/lo split ----------------
__global__ void wprep_kernel(const float* __restrict__ W) {
    __shared__ float tile[32][33];
    int k0 = blockIdx.x * 32, n0 = blockIdx.y * 32;
    int tx = threadIdx.x, ty = threadIdx.y;  // 32x8
    for (int i = ty; i < 32; i += 8)
        tile[i][tx] = W[(size_t)(k0 + i) * DIM + n0 + tx];
    __syncthreads();
    for (int i = ty; i < 32; i += 8) {
        int n = n0 + i, k = k0 + tx;
        float v = tile[tx][i];
        __nv_bfloat16 h = __float2bfloat16_rn(v);
        float lo = v - __bfloat162float(h);
        g_Whi[(size_t)n * HH + k] = h;
        g_Wlo[(size_t)n * HH + k] = __float2bfloat16_rn(lo);
    }
}

// ---------------- HMMA encode: 4-stage pipeline ----------------
// 512 threads, 16 warps (4x4), warp tile 32x32, CTA tile 128x128.
// KC=32, 32 chunks, 4 stages. Row stride 80B (conflict-free ldmatrix, no swizzle).
#define KC 32
#define NC (HH / KC)        // 32
#define RSTR 80
#define OFF_ALO 10240
#define OFF_BHI 20480
#define OFF_BLO 30720
#define STAGE   40960
#define NSTAGE  4
#define SMEM_ENC (512 + NSTAGE * STAGE)   // 164352

__global__ __launch_bounds__(512, 1)
void encode_tc_kernel(const float* __restrict__ qh, const float* __restrict__ dh,
                      const float* __restrict__ bias,
                      const int* __restrict__ qmask, const int* __restrict__ dmask)
{
    extern __shared__ __align__(128) char smem[];
    const uint32_t sb = smem_u32(smem);
    const int tid  = threadIdx.x;
    const int wid  = tid >> 5, lane = tid & 31;
    const int wm   = wid >> 2, wn = wid & 3;
    const int mb   = wm * 32, nb = wn * 32;
    const bool isQ = blockIdx.x < (QROWS / 128);
    const float* src = isQ ? qh + (size_t)blockIdx.x * 128 * HH
                           : dh + (size_t)(blockIdx.x - QROWS / 128) * 128 * HH;

    float* biasS = (float*)smem;
    if (tid < DIM) biasS[tid] = bias[tid];

    // staging coords: thread owns 8 floats of one row per chunk
    const int row = tid >> 2, q = tid & 3;
    const float* arow = src + (size_t)row * HH + q * 8;
    const uint32_t aDstOff = (uint32_t)(row * RSTR + q * 16);
    const __nv_bfloat16* whrow = g_Whi + (size_t)row * HH + q * 8;
    const __nv_bfloat16* wlrow = g_Wlo + (size_t)row * HH + q * 8;

    const uint32_t rowOffA = (uint32_t)((mb + (lane & 15)) * RSTR + (lane >> 4) * 16);
    const uint32_t rowOffB = (uint32_t)((nb + ((lane >> 4) & 1) * 8 + (lane & 7)) * RSTR
                                        + ((lane >> 3) & 1) * 16);

    float acc[2][4][4];
    #pragma unroll
    for (int mf = 0; mf < 2; mf++)
        #pragma unroll
        for (int nf = 0; nf < 4; nf++)
            #pragma unroll
            for (int j = 0; j < 4; j++) acc[mf][nf][j] = 0.0f;

    // ---- prologue: stage chunks 0..2 ----
    #pragma unroll
    for (int s = 0; s < 3; s++) {
        char* bp = smem + 512 + s * STAGE;
        uint32_t bsb = sb + 512 + s * STAGE;
        float4 f0 = *(const float4*)(arow + s * KC);
        float4 f1 = *(const float4*)(arow + s * KC + 4);
        uint4 hi = make_uint4(pack_bf2(f0.x, f0.y), pack_bf2(f0.z, f0.w),
                              pack_bf2(f1.x, f1.y), pack_bf2(f1.z, f1.w));
        uint4 lo = make_uint4(
            pack_bf2(f0.x - __bfloat162float(__float2bfloat16_rn(f0.x)),
                     f0.y - __bfloat162float(__float2bfloat16_rn(f0.y))),
            pack_bf2(f0.z - __bfloat162float(__float2bfloat16_rn(f0.z)),
                     f0.w - __bfloat162float(__float2bfloat16_rn(f0.w))),
            pack_bf2(f1.x - __bfloat162float(__float2bfloat16_rn(f1.x)),
                     f1.y - __bfloat162float(__float2bfloat16_rn(f1.y))),
            pack_bf2(f1.z - __bfloat162float(__float2bfloat16_rn(f1.z)),
                     f1.w - __bfloat162float(__float2bfloat16_rn(f1.w))));
        *(uint4*)(bp + aDstOff) = hi;
        *(uint4*)(bp + OFF_ALO + aDstOff) = lo;
        cp16(bsb + OFF_BHI + aDstOff, whrow + s * KC);
        cp16(bsb + OFF_BLO + aDstOff, wlrow + s * KC);
        CP_COMMIT();
    }

    for (int c = 0; c < NC; c++) {
        const int rem = NC - 1 - c;
        if (rem >= 2)      CP_WAITN(2);
        else if (rem == 1) CP_WAITN(1);
        else               CP_WAITN(0);
        __syncthreads();

        // stage chunk c+3: A LDG early, B cp.async + commit
        const int c3 = c + 3;
        float4 f0, f1;
        if (c3 < NC) {
            f0 = *(const float4*)(arow + c3 * KC);
            f1 = *(const float4*)(arow + c3 * KC + 4);
            uint32_t bsb = sb + 512 + (c3 & 3) * STAGE;
            cp16(bsb + OFF_BHI + aDstOff, whrow + c3 * KC);
            cp16(bsb + OFF_BLO + aDstOff, wlrow + c3 * KC);
            CP_COMMIT();
        }

        // ---- MMA on stage (c & 3): 2 ks steps ----
        const uint32_t base = sb + 512 + (c & 3) * STAGE;
        #pragma unroll
        for (int ks = 0; ks < 2; ks++) {
            uint32_t ah[2][4], al[2][4], bh[2][4], bl[2][4];
            #pragma unroll
            for (int mf = 0; mf < 2; mf++) {
                uint32_t ao = base + rowOffA + mf * (16 * RSTR) + ks * 32;
                ldmx4(ah[mf], ao);
                ldmx4(al[mf], ao + OFF_ALO);
            }
            #pragma unroll
            for (int p = 0; p < 2; p++) {
                uint32_t bo = base + rowOffB + p * (16 * RSTR) + ks * 32;
                ldmx4(bh[p], bo + OFF_BHI);
                ldmx4(bl[p], bo + OFF_BLO);
            }
            #pragma unroll
            for (int mf = 0; mf < 2; mf++)
                #pragma unroll
                for (int nf = 0; nf < 4; nf++)
                    mma16816(acc[mf][nf], ah[mf], &bh[nf >> 1][(nf & 1) * 2]);
            #pragma unroll
            for (int mf = 0; mf < 2; mf++)
                #pragma unroll
                for (int nf = 0; nf < 4; nf++)
                    mma16816(acc[mf][nf], al[mf], &bh[nf >> 1][(nf & 1) * 2]);
            #pragma unroll
            for (int mf = 0; mf < 2; mf++)
                #pragma unroll
                for (int nf = 0; nf < 4; nf++)
                    mma16816(acc[mf][nf], ah[mf], &bl[nf >> 1][(nf & 1) * 2]);
        }

        // convert + store A for chunk c+3 (LDG issued before MMA)
        if (c3 < NC) {
            char* bp = smem + 512 + (c3 & 3) * STAGE;
            uint4 hi = make_uint4(pack_bf2(f0.x, f0.y), pack_bf2(f0.z, f0.w),
                                  pack_bf2(f1.x, f1.y), pack_bf2(f1.z, f1.w));
            uint4 lo = make_uint4(
                pack_bf2(f0.x - __bfloat162float(__float2bfloat16_rn(f0.x)),
                         f0.y - __bfloat162float(__float2bfloat16_rn(f0.y))),
                pack_bf2(f0.z - __bfloat162float(__float2bfloat16_rn(f0.z)),
                         f0.w - __bfloat162float(__float2bfloat16_rn(f0.w))),
                pack_bf2(f1.x - __bfloat162float(__float2bfloat16_rn(f1.x)),
                         f1.y - __bfloat162float(__float2bfloat16_rn(f1.y))),
                pack_bf2(f1.z - __bfloat162float(__float2bfloat16_rn(f1.z)),
                         f1.w - __bfloat162float(__float2bfloat16_rn(f1.w))));
            *(uint4*)(bp + aDstOff) = hi;
            *(uint4*)(bp + OFF_ALO + aDstOff) = lo;
        }
    }

    // ---- epilogue ----
    __syncthreads();
    float* smemf = (float*)(smem + 512);   // [128][132]
    {
        float2 bnf[4];
        #pragma unroll
        for (int nf = 0; nf < 4; nf++) {
            int n0 = nb + nf * 8 + (lane & 3) * 2;
            bnf[nf] = make_float2(biasS[n0], biasS[n0 + 1]);
        }
        #pragma unroll
        for (int mf = 0; mf < 2; mf++) {
            int m0 = mb + mf * 16 + (lane >> 2);
            #pragma unroll
            for (int nf = 0; nf < 4; nf++) {
                int n0 = nb + nf * 8 + (lane & 3) * 2;
                *(float2*)&smemf[m0 * 132 + n0] =
                    make_float2(acc[mf][nf][0] + bnf[nf].x, acc[mf][nf][1] + bnf[nf].y);
                *(float2*)&smemf[(m0 + 8) * 132 + n0] =
                    make_float2(acc[mf][nf][2] + bnf[nf].x, acc[mf][nf][3] + bnf[nf].y);
            }
        }
    }
    __syncthreads();

    {
        int rrow = tid >> 2, qq = tid & 3;
        const float* rowp = &smemf[rrow * 132];
        float ss = 0.0f;
        #pragma unroll
        for (int j = 0; j < 32; j++) { float x = rowp[qq * 32 + j]; ss += x * x; }
        ss += __shfl_xor_sync(0xffffffffu, ss, 1);
        ss += __shfl_xor_sync(0xffffffffu, ss, 2);
        int grow = blockIdx.x * 128 + rrow;
        float m = isQ ? (float)qmask[grow] : (float)dmask[grow - QROWS];
        float sc = m / fmaxf(sqrtf(ss), 1e-12f);

        if (isQ) {
            int b = grow >> 6, qi = grow & 63;
            float* qp = g_qT + (size_t)b * DIM * LQ + qi;
            #pragma unroll
            for (int cc = 0; cc < 32; cc++) qp[(qq * 32 + cc) * LQ] = rowp[qq * 32 + cc] * sc;
        } else {
            float* dp = g_d + (size_t)(grow - QROWS) * DIM;
            #pragma unroll
            for (int cc = 0; cc < 32; cc += 4) {
                float4 v = *(const float4*)(rowp + qq * 32 + cc);
                *(float4*)(dp + qq * 32 + cc) = make_float4(v.x * sc, v.y * sc, v.z * sc, v.w * sc);
            }
        }
    }
}

// ---------------- segment-sum via atomics ----------------
__global__ void pool_accum_kernel(const int* __restrict__ dmask,
                                  const int* __restrict__ labels)
{
    int gwarp = (blockIdx.x * blockDim.x + threadIdx.x) >> 5;
    if (gwarp >= BB * LD) return;
    int b = gwarp / LD, t = gwarp % LD;
    if (dmask[b * LD + t] <= 0) return;
    int lane = threadIdx.x & 31;
    int seg  = labels[b * LD + t] % g_k[b];
    const float4 v = *(const float4*)(g_d + ((size_t)b * LD + t) * DIM + lane * 4);
    float* dst = g_sums + ((size_t)b * MAXK_MAX + seg) * DIM + lane * 4;
    atomicAdd(dst + 0, v.x); atomicAdd(dst + 1, v.y);
    atomicAdd(dst + 2, v.z); atomicAdd(dst + 3, v.w);
    if (lane == 0) atomicAdd(&g_counts[b * MAXK_MAX + seg], 1.0f);
}

// ---------------- mean + L2 normalize pooled clusters ----------------
__global__ void pool_norm_kernel() {
    int b = blockIdx.y, c = blockIdx.x;
    if (c >= g_k[b]) return;
    int t = threadIdx.x;
    float cnt = fmaxf(g_counts[b * MAXK_MAX + c], 1.0f);
    float v = g_sums[((size_t)b * MAXK_MAX + c) * DIM + t] / cnt;
    float ss = v * v;
    #pragma unroll
    for (int off = 16; off; off >>= 1) ss += __shfl_xor_sync(0xffffffffu, ss, off);
    __shared__ float red[4];
    int warp = t >> 5, lane = t & 31;
    if (lane == 0) red[warp] = ss;
    __syncthreads();
    float tot = red[0] + red[1] + red[2] + red[3];
    float inv = 1.0f / fmaxf(sqrtf(tot), 1e-12f);
    g_pool[((size_t)b * MAXK_MAX + c) * DIM + t] = v * inv;
}

// ---------------- sim GEMM + running max ----------------
__global__ __launch_bounds__(256) void score_kernel() {
    const int b  = blockIdx.y;
    const int kb = g_k[b];
    const int c0 = blockIdx.x * 64;
    if (c0 >= kb) return;

    __shared__ float As[64][40];
    __shared__ float Bs[32][64];

    const int tid  = threadIdx.x;
    const int warp = tid >> 5, lane = tid & 31;
    const int rowBase = warp * 8;
    const int colBase = lane * 2;

    float acc[8][2];
    #pragma unroll
    for (int r = 0; r < 8; r++) { acc[r][0] = 0.0f; acc[r][1] = 0.0f; }

    const float* poolB = g_pool + (size_t)b * MAXK_MAX * DIM;
    const float* qT    = g_qT + (size_t)b * DIM * LQ;

    for (int k0 = 0; k0 < DIM; k0 += 32) {
        #pragma unroll
        for (int i = 0; i < 2; i++) {
            int s = tid + 256 * i;
            int r = s >> 3, kk = (s & 7) * 4;
            float4 v = make_float4(0.f, 0.f, 0.f, 0.f);
            if (c0 + r < kb)
                v = *(const float4*)(poolB + (size_t)(c0 + r) * DIM + k0 + kk);
            *(float4*)&As[r][kk] = v;
        }
        #pragma unroll
        for (int i = 0; i < 2; i++) {
            int s = tid + 256 * i;
            int kk = s >> 4, q4 = (s & 15) * 4;
            float4 v = *(const float4*)(qT + (size_t)(k0 + kk) * LQ + q4);
            *(float4*)&Bs[kk][q4] = v;
        }
        __syncthreads();
        #pragma unroll
        for (int kk = 0; kk < 32; kk++) {
            float2 bv = *(const float2*)&Bs[kk][colBase];
            #pragma unroll
            for (int r = 0; r < 8; r++) {
                float a = As[rowBase + r][kk];
                acc[r][0] += a * bv.x;
                acc[r][1] += a * bv.y;
            }
        }
        __syncthreads();
    }

    float m0 = -1e4f, m1 = -1e4f;
    #pragma unroll
    for (int r = 0; r < 8; r++) {
        if (c0 + rowBase + r < kb) {
            m0 = fmaxf(m0, acc[r][0]);
            m1 = fmaxf(m1, acc[r][1]);
        }
    }
    atomicMax(&g_simmax[b * LQ + colBase],     enc_f(m0));
    atomicMax(&g_simmax[b * LQ + colBase + 1], enc_f(m1));
}

// ---------------- finalize ----------------
__global__ void finalize_kernel(const int* __restrict__ qmask, float* __restrict__ out) {
    int b = blockIdx.x, q = threadIdx.x;
    float v = dec_f(g_simmax[b * LQ + q]) * (float)qmask[b * LQ + q];
    #pragma unroll
    for (int off = 16; off; off >>= 1) v += __shfl_xor_sync(0xffffffffu, v, off);
    __shared__ float sm[2];
    int warp = q >> 5, lane = q & 31;
    if (lane == 0) sm[warp] = v;
    __syncthreads();
    if (q == 0) out[b] = sm[0] + sm[1];
}

// ---------------- launch ----------------
extern "C" void kernel_launch(void* const* d_in, const int* in_sizes, int n_in,
                              void* d_out, int out_size)
{
    const float* qh    = (const float*)d_in[0];
    const float* dh    = (const float*)d_in[1];
    const float* Wm    = (const float*)d_in[2];
    const float* bias  = (const float*)d_in[3];
    const int*   qmask = (const int*)d_in[4];
    const int*   dmask = (const int*)d_in[5];
    const int*   labels= (const int*)d_in[6];
    const int*   pfp   = (n_in > 7) ? (const int*)d_in[7] : nullptr;
    float* out = (float*)d_out;

    static int smem_set = 0;
    if (!smem_set) {
        cudaFuncSetAttribute(encode_tc_kernel,
                             cudaFuncAttributeMaxDynamicSharedMemorySize, SMEM_ENC);
        smem_set = 1;
    }

    k_kernel<<<BB, 256>>>(dmask, pfp);
    {
        dim3 grid(24, BB);
        init_kernel<<<grid, 256>>>();
    }
    {
        dim3 grid(HH / 32, DIM / 32), blk(32, 8);
        wprep_kernel<<<grid, blk>>>(Wm);
    }
    encode_tc_kernel<<<NROWS / 128, 512, SMEM_ENC>>>(qh, dh, bias, qmask, dmask);
    pool_accum_kernel<<<BB * LD / 8, 256>>>(dmask, labels);
    {
        dim3 grid(MAXK_MAX, BB);
        pool_norm_kernel<<<grid, 128>>>();
    }
    {
        dim3 grid((MAXK_MAX + 63) / 64, BB);
        score_kernel<<<grid, 256>>>();
    }
    finalize_kernel<<<BB, 64>>>(qmask, out);
}